// round 1
// baseline (speedup 1.0000x reference)
#include <cuda_runtime.h>
#include <math.h>

#define HIDDEN 768
#define S_LEN  2048
#define B_SZ   4
#define NH     12
#define HD     64
#define M_TOTAL (B_SZ * S_LEN)   // 8192

// Scratch (device globals: allocation-free per harness rules)
__device__ float g_Q[M_TOTAL * HIDDEN];
__device__ float g_K[M_TOTAL * HIDDEN];
__device__ float g_V[M_TOTAL * HIDDEN];
__device__ float g_C[M_TOTAL * HIDDEN];

// ---------------------------------------------------------------------------
// GEMM:  C[M,N] = A[M,K] @ W[N,K]^T + bias[N]
// 64x64 tile, BK=16, 256 threads, 4x4 per-thread register tile.
// A and W tiles stored k-major-transposed in smem -> LDS.128 in inner loop.
// ---------------------------------------------------------------------------
__global__ __launch_bounds__(256, 4)
void gemm_bias_kernel(const float* __restrict__ A, const float* __restrict__ W,
                      const float* __restrict__ bias, float* __restrict__ C,
                      int M, int N, int K)
{
    __shared__ float As[16][64];
    __shared__ float Ws[16][64];

    const int bm = blockIdx.y * 64;
    const int bn = blockIdx.x * 64;
    const int tid = threadIdx.x;
    const int r0 = (tid >> 4) << 2;   // 0..60 step 4
    const int c0 = (tid & 15) << 2;   // 0..60 step 4
    const int lr = tid >> 2;          // 0..63 load row
    const int lk = (tid & 3) << 2;    // 0,4,8,12

    float acc[4][4] = {};

    const float* Arow = A + (size_t)(bm + lr) * K + lk;
    const float* Wrow = W + (size_t)(bn + lr) * K + lk;

    for (int k0 = 0; k0 < K; k0 += 16) {
        float4 av = *(const float4*)(Arow + k0);
        float4 wv = *(const float4*)(Wrow + k0);
        As[lk + 0][lr] = av.x; As[lk + 1][lr] = av.y;
        As[lk + 2][lr] = av.z; As[lk + 3][lr] = av.w;
        Ws[lk + 0][lr] = wv.x; Ws[lk + 1][lr] = wv.y;
        Ws[lk + 2][lr] = wv.z; Ws[lk + 3][lr] = wv.w;
        __syncthreads();

        #pragma unroll
        for (int kk = 0; kk < 16; kk++) {
            float4 a = *(const float4*)&As[kk][r0];
            float4 w = *(const float4*)&Ws[kk][c0];
            acc[0][0] += a.x * w.x; acc[0][1] += a.x * w.y;
            acc[0][2] += a.x * w.z; acc[0][3] += a.x * w.w;
            acc[1][0] += a.y * w.x; acc[1][1] += a.y * w.y;
            acc[1][2] += a.y * w.z; acc[1][3] += a.y * w.w;
            acc[2][0] += a.z * w.x; acc[2][1] += a.z * w.y;
            acc[2][2] += a.z * w.z; acc[2][3] += a.z * w.w;
            acc[3][0] += a.w * w.x; acc[3][1] += a.w * w.y;
            acc[3][2] += a.w * w.z; acc[3][3] += a.w * w.w;
        }
        __syncthreads();
    }

    float4 bv = *(const float4*)&bias[bn + c0];
    #pragma unroll
    for (int i = 0; i < 4; i++) {
        float4 o;
        o.x = acc[i][0] + bv.x;
        o.y = acc[i][1] + bv.y;
        o.z = acc[i][2] + bv.z;
        o.w = acc[i][3] + bv.w;
        *(float4*)&C[(size_t)(bm + r0 + i) * N + bn + c0] = o;
    }
}

// ---------------------------------------------------------------------------
// Flash attention (fp32, online softmax).
// grid = (S/64, NH, B), block = 256. Each block: 64 queries x 1 head.
// smem layout (floats):
//   Qs[64][64]  d-major   (scaled by 1/sqrt(64))
//   Ks[64][64]  d-major
//   Vs[64][64]  k-major (natural)
//   Ss[64][65]  scores / probs (padded)
//   Mr[64], Lr[64], Al[64], Bi[64]
// ---------------------------------------------------------------------------
#define Q_OFF  0
#define K_OFF  4096
#define V_OFF  8192
#define S_OFF  12288
#define SROW   65
#define M_OFF  (S_OFF + 64 * SROW)     // 16448
#define L_OFF  (M_OFF + 64)
#define A_OFF  (L_OFF + 64)
#define BI_OFF (A_OFF + 64)
#define SMEM_FLOATS (BI_OFF + 64)      // 16704
#define ATTN_SMEM_BYTES (SMEM_FLOATS * 4)

__global__ __launch_bounds__(256, 2)
void attn_kernel(const float* __restrict__ Q, const float* __restrict__ K,
                 const float* __restrict__ V, const float* __restrict__ mask,
                 float* __restrict__ Ctx)
{
    extern __shared__ float sm[];
    float* Qs = sm + Q_OFF;
    float* Ks = sm + K_OFF;
    float* Vs = sm + V_OFF;
    float* Ss = sm + S_OFF;
    float* Mr = sm + M_OFF;
    float* Lr = sm + L_OFF;
    float* Al = sm + A_OFF;
    float* Bi = sm + BI_OFF;

    const int b  = blockIdx.z;
    const int h  = blockIdx.y;
    const int qt = blockIdx.x;
    const int tid = threadIdx.x;

    const int r0 = (tid >> 4) << 2;
    const int c0 = (tid & 15) << 2;
    const int lr = tid >> 2;          // 0..63
    const int ds = (tid & 3) << 4;    // 0,16,32,48

    const float scale = 0.125f;       // 1/sqrt(64)

    // Load Q tile (d-major, pre-scaled)
    const float* Qb = Q + ((size_t)b * S_LEN + (size_t)qt * 64) * HIDDEN + h * HD;
    #pragma unroll
    for (int rep = 0; rep < 4; rep++) {
        int d = ds + rep * 4;
        float4 v = *(const float4*)(Qb + (size_t)lr * HIDDEN + d);
        Qs[(d + 0) * 64 + lr] = v.x * scale;
        Qs[(d + 1) * 64 + lr] = v.y * scale;
        Qs[(d + 2) * 64 + lr] = v.z * scale;
        Qs[(d + 3) * 64 + lr] = v.w * scale;
    }
    if (tid < 64) {
        Mr[tid] = -3.0e38f;
        Lr[tid] = 0.0f;
    }
    __syncthreads();

    float o[4][4] = {};

    for (int kt = 0; kt < S_LEN / 64; kt++) {
        // Load K (d-major) and V (k-major) tiles + mask bias
        const float* Kb = K + ((size_t)b * S_LEN + (size_t)kt * 64) * HIDDEN + h * HD;
        const float* Vb = V + ((size_t)b * S_LEN + (size_t)kt * 64) * HIDDEN + h * HD;
        #pragma unroll
        for (int rep = 0; rep < 4; rep++) {
            int d = ds + rep * 4;
            float4 kv = *(const float4*)(Kb + (size_t)lr * HIDDEN + d);
            Ks[(d + 0) * 64 + lr] = kv.x;
            Ks[(d + 1) * 64 + lr] = kv.y;
            Ks[(d + 2) * 64 + lr] = kv.z;
            Ks[(d + 3) * 64 + lr] = kv.w;
            float4 vv = *(const float4*)(Vb + (size_t)lr * HIDDEN + d);
            *(float4*)&Vs[lr * 64 + d] = vv;
        }
        if (tid < 64)
            Bi[tid] = (1.0f - mask[(size_t)b * S_LEN + kt * 64 + tid]) * -10000.0f;
        __syncthreads();

        // S = Q K^T
        float sacc[4][4] = {};
        #pragma unroll 8
        for (int d = 0; d < 64; d++) {
            float4 a = *(const float4*)&Qs[d * 64 + r0];
            float4 kk = *(const float4*)&Ks[d * 64 + c0];
            sacc[0][0] += a.x * kk.x; sacc[0][1] += a.x * kk.y;
            sacc[0][2] += a.x * kk.z; sacc[0][3] += a.x * kk.w;
            sacc[1][0] += a.y * kk.x; sacc[1][1] += a.y * kk.y;
            sacc[1][2] += a.y * kk.z; sacc[1][3] += a.y * kk.w;
            sacc[2][0] += a.z * kk.x; sacc[2][1] += a.z * kk.y;
            sacc[2][2] += a.z * kk.z; sacc[2][3] += a.z * kk.w;
            sacc[3][0] += a.w * kk.x; sacc[3][1] += a.w * kk.y;
            sacc[3][2] += a.w * kk.z; sacc[3][3] += a.w * kk.w;
        }
        #pragma unroll
        for (int i = 0; i < 4; i++)
            #pragma unroll
            for (int j = 0; j < 4; j++)
                Ss[(r0 + i) * SROW + c0 + j] = sacc[i][j];
        __syncthreads();

        // Online softmax per row (threads 0..63)
        if (tid < 64) {
            const int r = tid;
            float mold = Mr[r];
            float mx = mold;
            #pragma unroll 8
            for (int k = 0; k < 64; k++) {
                float v = Ss[r * SROW + k] + Bi[k];
                Ss[r * SROW + k] = v;
                mx = fmaxf(mx, v);
            }
            float sum = 0.0f;
            #pragma unroll 8
            for (int k = 0; k < 64; k++) {
                float p = __expf(Ss[r * SROW + k] - mx);
                Ss[r * SROW + k] = p;
                sum += p;
            }
            float alpha = __expf(mold - mx);
            Al[r] = alpha;
            Mr[r] = mx;
            Lr[r] = Lr[r] * alpha + sum;
        }
        __syncthreads();

        // O = O*alpha + P V
        float a0 = Al[r0 + 0], a1 = Al[r0 + 1], a2 = Al[r0 + 2], a3 = Al[r0 + 3];
        #pragma unroll
        for (int j = 0; j < 4; j++) {
            o[0][j] *= a0; o[1][j] *= a1; o[2][j] *= a2; o[3][j] *= a3;
        }
        #pragma unroll 8
        for (int k = 0; k < 64; k++) {
            float4 vv = *(const float4*)&Vs[k * 64 + c0];
            float p0 = Ss[(r0 + 0) * SROW + k];
            float p1 = Ss[(r0 + 1) * SROW + k];
            float p2 = Ss[(r0 + 2) * SROW + k];
            float p3 = Ss[(r0 + 3) * SROW + k];
            o[0][0] += p0 * vv.x; o[0][1] += p0 * vv.y; o[0][2] += p0 * vv.z; o[0][3] += p0 * vv.w;
            o[1][0] += p1 * vv.x; o[1][1] += p1 * vv.y; o[1][2] += p1 * vv.z; o[1][3] += p1 * vv.w;
            o[2][0] += p2 * vv.x; o[2][1] += p2 * vv.y; o[2][2] += p2 * vv.z; o[2][3] += p2 * vv.w;
            o[3][0] += p3 * vv.x; o[3][1] += p3 * vv.y; o[3][2] += p3 * vv.z; o[3][3] += p3 * vv.w;
        }
        __syncthreads();
    }

    // Normalize and write context: [b, s, h*64 + d]
    float inv0 = 1.0f / Lr[r0 + 0];
    float inv1 = 1.0f / Lr[r0 + 1];
    float inv2 = 1.0f / Lr[r0 + 2];
    float inv3 = 1.0f / Lr[r0 + 3];
    float* Cb = Ctx + ((size_t)b * S_LEN + (size_t)qt * 64) * HIDDEN + h * HD;
    #pragma unroll
    for (int j = 0; j < 4; j++) {
        Cb[(size_t)(r0 + 0) * HIDDEN + c0 + j] = o[0][j] * inv0;
        Cb[(size_t)(r0 + 1) * HIDDEN + c0 + j] = o[1][j] * inv1;
        Cb[(size_t)(r0 + 2) * HIDDEN + c0 + j] = o[2][j] * inv2;
        Cb[(size_t)(r0 + 3) * HIDDEN + c0 + j] = o[3][j] * inv3;
    }
}

// ---------------------------------------------------------------------------
extern "C" void kernel_launch(void* const* d_in, const int* in_sizes, int n_in,
                              void* d_out, int out_size)
{
    const float* X    = (const float*)d_in[0];
    const float* mask = (const float*)d_in[1];
    const float* Wq   = (const float*)d_in[2];
    const float* bq   = (const float*)d_in[3];
    const float* Wk   = (const float*)d_in[4];
    const float* bk   = (const float*)d_in[5];
    const float* Wv   = (const float*)d_in[6];
    const float* bv   = (const float*)d_in[7];
    const float* Wo   = (const float*)d_in[8];
    const float* bo   = (const float*)d_in[9];
    float* out = (float*)d_out;

    float *gQ, *gK, *gV, *gC;
    cudaGetSymbolAddress((void**)&gQ, g_Q);
    cudaGetSymbolAddress((void**)&gK, g_K);
    cudaGetSymbolAddress((void**)&gV, g_V);
    cudaGetSymbolAddress((void**)&gC, g_C);

    cudaFuncSetAttribute(attn_kernel,
                         cudaFuncAttributeMaxDynamicSharedMemorySize,
                         ATTN_SMEM_BYTES);

    dim3 ggrid(HIDDEN / 64, M_TOTAL / 64);   // (12, 128)
    gemm_bias_kernel<<<ggrid, 256>>>(X, Wq, bq, gQ, M_TOTAL, HIDDEN, HIDDEN);
    gemm_bias_kernel<<<ggrid, 256>>>(X, Wk, bk, gK, M_TOTAL, HIDDEN, HIDDEN);
    gemm_bias_kernel<<<ggrid, 256>>>(X, Wv, bv, gV, M_TOTAL, HIDDEN, HIDDEN);

    dim3 agrid(S_LEN / 64, NH, B_SZ);        // (32, 12, 4)
    attn_kernel<<<agrid, 256, ATTN_SMEM_BYTES>>>(gQ, gK, gV, mask, gC);

    gemm_bias_kernel<<<ggrid, 256>>>(gC, Wo, bo, out, M_TOTAL, HIDDEN, HIDDEN);
}

// round 3
// speedup vs baseline: 1.3191x; 1.3191x over previous
#include <cuda_runtime.h>
#include <cuda_bf16.h>
#include <cstdint>
#include <math.h>

#define HIDDEN 768
#define S_LEN  2048
#define B_SZ   4
#define NH     12
#define HD     64
#define M_TOTAL (B_SZ * S_LEN)   // 8192
#define GK 768

// Scratch (device globals: allocation-free per harness rules)
__device__ float g_Q[M_TOTAL * HIDDEN];
__device__ float g_K[M_TOTAL * HIDDEN];
__device__ float g_V[M_TOTAL * HIDDEN];
__device__ float g_C[M_TOTAL * HIDDEN];

// ===========================================================================
// Warp MMA helpers (base sm_103 PTX: ldmatrix + mma.sync, sm_80-era features)
// ===========================================================================
__device__ __forceinline__ uint32_t smem_u32(const void* p) {
    uint32_t a;
    asm("{ .reg .u64 t; cvta.to.shared.u64 t, %1; cvt.u32.u64 %0, t; }"
        : "=r"(a) : "l"(p));
    return a;
}

__device__ __forceinline__ void ldsm_x4(uint32_t addr, uint32_t* r) {
    asm volatile("ldmatrix.sync.aligned.m8n8.x4.shared.b16 {%0,%1,%2,%3}, [%4];"
        : "=r"(r[0]), "=r"(r[1]), "=r"(r[2]), "=r"(r[3]) : "r"(addr));
}

__device__ __forceinline__ void mma_bf16(float* d, const uint32_t* a,
                                         uint32_t b0, uint32_t b1) {
    asm volatile(
        "mma.sync.aligned.m16n8k16.row.col.f32.bf16.bf16.f32 "
        "{%0,%1,%2,%3}, {%4,%5,%6,%7}, {%8,%9}, {%0,%1,%2,%3};"
        : "+f"(d[0]), "+f"(d[1]), "+f"(d[2]), "+f"(d[3])
        : "r"(a[0]), "r"(a[1]), "r"(a[2]), "r"(a[3]), "r"(b0), "r"(b1));
}

// ===========================================================================
// GEMM: C[M,N] = A[M,K] @ W[N,K]^T + bias, via mma.sync bf16 split-precision.
// CTA tile 128x128, BK=32, 8 warps (2x4), warp tile 64x32.
// smem: per stage, 4 tiles [128][40] bf16 (A_hi, A_lo, W_hi, W_lo), 2 stages.
// ===========================================================================
#define BK 32
#define KSTEPS (GK / BK)          // 24
#define LDSTR 40                  // bf16 elements per smem row (80 bytes)
#define TILE_B (128 * LDSTR * 2)  // 10240 bytes
#define STAGE_B (4 * TILE_B)      // 40960
#define GEMM_SMEM_BYTES (2 * STAGE_B)  // 81920

#define AH_O 0
#define AL_O TILE_B
#define WH_O (2 * TILE_B)
#define WL_O (3 * TILE_B)

__device__ __forceinline__ void split4(float4 v, uint2& hi, uint2& lo) {
    __nv_bfloat162 h0 = __floats2bfloat162_rn(v.x, v.y);
    __nv_bfloat162 h1 = __floats2bfloat162_rn(v.z, v.w);
    __nv_bfloat162 l0 = __floats2bfloat162_rn(v.x - __bfloat162float(h0.x),
                                              v.y - __bfloat162float(h0.y));
    __nv_bfloat162 l1 = __floats2bfloat162_rn(v.z - __bfloat162float(h1.x),
                                              v.w - __bfloat162float(h1.y));
    hi.x = *(uint32_t*)&h0; hi.y = *(uint32_t*)&h1;
    lo.x = *(uint32_t*)&l0; lo.y = *(uint32_t*)&l1;
}

__global__ __launch_bounds__(256, 1)
void gemm_mma_kernel(const float* __restrict__ A, const float* __restrict__ W,
                     const float* __restrict__ bias, float* __restrict__ C)
{
    extern __shared__ char smc[];
    const uint32_t sb = smem_u32(smc);
    const int tid  = threadIdx.x;
    const int lane = tid & 31;
    const int wid  = tid >> 5;
    const int bm = blockIdx.y * 128;
    const int bn = blockIdx.x * 128;
    const int wm = (wid & 1) * 64;     // warp M offset in tile
    const int wn = (wid >> 1) * 32;    // warp N offset in tile

    // Loader mapping: rep r, thread t -> row = r*32 + t/8, k = (t%8)*4
    const int lr_row = tid >> 3;       // 0..31 (plus rep*32)
    const int lr_k   = (tid & 7) * 4;

    float4 aV[4], wV[4];

    // ---- prologue: load k-step 0 and stage into smem buffer 0
    {
        const float* Ab = A + (size_t)bm * GK;
        const float* Wb = W + (size_t)bn * GK;
        #pragma unroll
        for (int rep = 0; rep < 4; rep++) {
            int row = rep * 32 + lr_row;
            aV[rep] = *(const float4*)(Ab + (size_t)row * GK + lr_k);
            wV[rep] = *(const float4*)(Wb + (size_t)row * GK + lr_k);
        }
        #pragma unroll
        for (int rep = 0; rep < 4; rep++) {
            int row = rep * 32 + lr_row;
            uint32_t off = (uint32_t)(row * (LDSTR * 2) + lr_k * 2);
            uint2 hi, lo;
            split4(aV[rep], hi, lo);
            *(uint2*)(smc + AH_O + off) = hi;
            *(uint2*)(smc + AL_O + off) = lo;
            split4(wV[rep], hi, lo);
            *(uint2*)(smc + WH_O + off) = hi;
            *(uint2*)(smc + WL_O + off) = lo;
        }
    }
    __syncthreads();

    float acc[4][4][4] = {};

    // ldmatrix lane addressing (same formula for A and W):
    // row_in_16 = lane&15, k_off = 8*(lane>>4)
    const int frag_r = lane & 15;
    const int frag_k = (lane >> 4) << 3;

    for (int s = 0; s < KSTEPS; s++) {
        // load next k-step global -> regs
        if (s + 1 < KSTEPS) {
            const float* Ab = A + (size_t)bm * GK + (s + 1) * BK;
            const float* Wb = W + (size_t)bn * GK + (s + 1) * BK;
            #pragma unroll
            for (int rep = 0; rep < 4; rep++) {
                int row = rep * 32 + lr_row;
                aV[rep] = *(const float4*)(Ab + (size_t)row * GK + lr_k);
                wV[rep] = *(const float4*)(Wb + (size_t)row * GK + lr_k);
            }
        }

        // compute from stage (s&1)
        const uint32_t stg = sb + (uint32_t)((s & 1) * STAGE_B);
        #pragma unroll
        for (int kk = 0; kk < 2; kk++) {
            const uint32_t kbyte = (uint32_t)((kk * 16 + frag_k) * 2);
            uint32_t ah[4][4], al[4][4], wh[2][4], wl[2][4];
            #pragma unroll
            for (int mi = 0; mi < 4; mi++) {
                uint32_t ro = (uint32_t)((wm + mi * 16 + frag_r) * (LDSTR * 2)) + kbyte;
                ldsm_x4(stg + AH_O + ro, ah[mi]);
                ldsm_x4(stg + AL_O + ro, al[mi]);
            }
            #pragma unroll
            for (int np = 0; np < 2; np++) {
                uint32_t ro = (uint32_t)((wn + np * 16 + frag_r) * (LDSTR * 2)) + kbyte;
                ldsm_x4(stg + WH_O + ro, wh[np]);
                ldsm_x4(stg + WL_O + ro, wl[np]);
            }
            #pragma unroll
            for (int mi = 0; mi < 4; mi++) {
                #pragma unroll
                for (int nj = 0; nj < 4; nj++) {
                    const int np = nj >> 1, sub = nj & 1;
                    uint32_t bh0 = wh[np][sub], bh1 = wh[np][sub + 2];
                    uint32_t bl0 = wl[np][sub], bl1 = wl[np][sub + 2];
                    mma_bf16(acc[mi][nj], ah[mi], bh0, bh1);
                    mma_bf16(acc[mi][nj], ah[mi], bl0, bl1);
                    mma_bf16(acc[mi][nj], al[mi], bh0, bh1);
                }
            }
        }
        __syncthreads();

        // stage next tile into the other buffer
        if (s + 1 < KSTEPS) {
            char* dst = smc + ((s + 1) & 1) * STAGE_B;
            #pragma unroll
            for (int rep = 0; rep < 4; rep++) {
                int row = rep * 32 + lr_row;
                uint32_t off = (uint32_t)(row * (LDSTR * 2) + lr_k * 2);
                uint2 hi, lo;
                split4(aV[rep], hi, lo);
                *(uint2*)(dst + AH_O + off) = hi;
                *(uint2*)(dst + AL_O + off) = lo;
                split4(wV[rep], hi, lo);
                *(uint2*)(dst + WH_O + off) = hi;
                *(uint2*)(dst + WL_O + off) = lo;
            }
            __syncthreads();
        }
    }

    // ---- epilogue: acc -> C (+bias)
    const int gr = lane >> 2;          // 0..7
    const int cp = (lane & 3) * 2;
    #pragma unroll
    for (int mi = 0; mi < 4; mi++) {
        #pragma unroll
        for (int nj = 0; nj < 4; nj++) {
            int row0 = bm + wm + mi * 16 + gr;
            int col  = bn + wn + nj * 8 + cp;
            float b0 = bias[col], b1 = bias[col + 1];
            float2 v0 = { acc[mi][nj][0] + b0, acc[mi][nj][1] + b1 };
            float2 v1 = { acc[mi][nj][2] + b0, acc[mi][nj][3] + b1 };
            *(float2*)&C[(size_t)row0 * GK + col] = v0;
            *(float2*)&C[(size_t)(row0 + 8) * GK + col] = v1;
        }
    }
}

// ---------------------------------------------------------------------------
// Flash attention (fp32, online softmax) — unchanged (known-good from R1).
// ---------------------------------------------------------------------------
#define Q_OFF  0
#define K_OFF  4096
#define V_OFF  8192
#define S_OFF  12288
#define SROW   65
#define M_OFF  (S_OFF + 64 * SROW)
#define L_OFF  (M_OFF + 64)
#define A_OFF  (L_OFF + 64)
#define BI_OFF (A_OFF + 64)
#define SMEM_FLOATS (BI_OFF + 64)
#define ATTN_SMEM_BYTES (SMEM_FLOATS * 4)

__global__ __launch_bounds__(256, 2)
void attn_kernel(const float* __restrict__ Q, const float* __restrict__ K,
                 const float* __restrict__ V, const float* __restrict__ mask,
                 float* __restrict__ Ctx)
{
    extern __shared__ float smf[];
    float* Qs = smf + Q_OFF;
    float* Ks = smf + K_OFF;
    float* Vs = smf + V_OFF;
    float* Ss = smf + S_OFF;
    float* Mr = smf + M_OFF;
    float* Lr = smf + L_OFF;
    float* Al = smf + A_OFF;
    float* Bi = smf + BI_OFF;

    const int b  = blockIdx.z;
    const int h  = blockIdx.y;
    const int qt = blockIdx.x;
    const int tid = threadIdx.x;

    const int r0 = (tid >> 4) << 2;
    const int c0 = (tid & 15) << 2;
    const int lr = tid >> 2;
    const int ds = (tid & 3) << 4;

    const float scale = 0.125f;

    const float* Qb = Q + ((size_t)b * S_LEN + (size_t)qt * 64) * HIDDEN + h * HD;
    #pragma unroll
    for (int rep = 0; rep < 4; rep++) {
        int d = ds + rep * 4;
        float4 v = *(const float4*)(Qb + (size_t)lr * HIDDEN + d);
        Qs[(d + 0) * 64 + lr] = v.x * scale;
        Qs[(d + 1) * 64 + lr] = v.y * scale;
        Qs[(d + 2) * 64 + lr] = v.z * scale;
        Qs[(d + 3) * 64 + lr] = v.w * scale;
    }
    if (tid < 64) {
        Mr[tid] = -3.0e38f;
        Lr[tid] = 0.0f;
    }
    __syncthreads();

    float o[4][4] = {};

    for (int kt = 0; kt < S_LEN / 64; kt++) {
        const float* Kb = K + ((size_t)b * S_LEN + (size_t)kt * 64) * HIDDEN + h * HD;
        const float* Vb = V + ((size_t)b * S_LEN + (size_t)kt * 64) * HIDDEN + h * HD;
        #pragma unroll
        for (int rep = 0; rep < 4; rep++) {
            int d = ds + rep * 4;
            float4 kv = *(const float4*)(Kb + (size_t)lr * HIDDEN + d);
            Ks[(d + 0) * 64 + lr] = kv.x;
            Ks[(d + 1) * 64 + lr] = kv.y;
            Ks[(d + 2) * 64 + lr] = kv.z;
            Ks[(d + 3) * 64 + lr] = kv.w;
            float4 vv = *(const float4*)(Vb + (size_t)lr * HIDDEN + d);
            *(float4*)&Vs[lr * 64 + d] = vv;
        }
        if (tid < 64)
            Bi[tid] = (1.0f - mask[(size_t)b * S_LEN + kt * 64 + tid]) * -10000.0f;
        __syncthreads();

        float sacc[4][4] = {};
        #pragma unroll 8
        for (int d = 0; d < 64; d++) {
            float4 a = *(const float4*)&Qs[d * 64 + r0];
            float4 kk = *(const float4*)&Ks[d * 64 + c0];
            sacc[0][0] += a.x * kk.x; sacc[0][1] += a.x * kk.y;
            sacc[0][2] += a.x * kk.z; sacc[0][3] += a.x * kk.w;
            sacc[1][0] += a.y * kk.x; sacc[1][1] += a.y * kk.y;
            sacc[1][2] += a.y * kk.z; sacc[1][3] += a.y * kk.w;
            sacc[2][0] += a.z * kk.x; sacc[2][1] += a.z * kk.y;
            sacc[2][2] += a.z * kk.z; sacc[2][3] += a.z * kk.w;
            sacc[3][0] += a.w * kk.x; sacc[3][1] += a.w * kk.y;
            sacc[3][2] += a.w * kk.z; sacc[3][3] += a.w * kk.w;
        }
        #pragma unroll
        for (int i = 0; i < 4; i++)
            #pragma unroll
            for (int j = 0; j < 4; j++)
                Ss[(r0 + i) * SROW + c0 + j] = sacc[i][j];
        __syncthreads();

        if (tid < 64) {
            const int r = tid;
            float mold = Mr[r];
            float mx = mold;
            #pragma unroll 8
            for (int k = 0; k < 64; k++) {
                float v = Ss[r * SROW + k] + Bi[k];
                Ss[r * SROW + k] = v;
                mx = fmaxf(mx, v);
            }
            float sum = 0.0f;
            #pragma unroll 8
            for (int k = 0; k < 64; k++) {
                float p = __expf(Ss[r * SROW + k] - mx);
                Ss[r * SROW + k] = p;
                sum += p;
            }
            float alpha = __expf(mold - mx);
            Al[r] = alpha;
            Mr[r] = mx;
            Lr[r] = Lr[r] * alpha + sum;
        }
        __syncthreads();

        float a0 = Al[r0 + 0], a1 = Al[r0 + 1], a2 = Al[r0 + 2], a3 = Al[r0 + 3];
        #pragma unroll
        for (int j = 0; j < 4; j++) {
            o[0][j] *= a0; o[1][j] *= a1; o[2][j] *= a2; o[3][j] *= a3;
        }
        #pragma unroll 8
        for (int k = 0; k < 64; k++) {
            float4 vv = *(const float4*)&Vs[k * 64 + c0];
            float p0 = Ss[(r0 + 0) * SROW + k];
            float p1 = Ss[(r0 + 1) * SROW + k];
            float p2 = Ss[(r0 + 2) * SROW + k];
            float p3 = Ss[(r0 + 3) * SROW + k];
            o[0][0] += p0 * vv.x; o[0][1] += p0 * vv.y; o[0][2] += p0 * vv.z; o[0][3] += p0 * vv.w;
            o[1][0] += p1 * vv.x; o[1][1] += p1 * vv.y; o[1][2] += p1 * vv.z; o[1][3] += p1 * vv.w;
            o[2][0] += p2 * vv.x; o[2][1] += p2 * vv.y; o[2][2] += p2 * vv.z; o[2][3] += p2 * vv.w;
            o[3][0] += p3 * vv.x; o[3][1] += p3 * vv.y; o[3][2] += p3 * vv.z; o[3][3] += p3 * vv.w;
        }
        __syncthreads();
    }

    float inv0 = 1.0f / Lr[r0 + 0];
    float inv1 = 1.0f / Lr[r0 + 1];
    float inv2 = 1.0f / Lr[r0 + 2];
    float inv3 = 1.0f / Lr[r0 + 3];
    float* Cb = Ctx + ((size_t)b * S_LEN + (size_t)qt * 64) * HIDDEN + h * HD;
    #pragma unroll
    for (int j = 0; j < 4; j++) {
        Cb[(size_t)(r0 + 0) * HIDDEN + c0 + j] = o[0][j] * inv0;
        Cb[(size_t)(r0 + 1) * HIDDEN + c0 + j] = o[1][j] * inv1;
        Cb[(size_t)(r0 + 2) * HIDDEN + c0 + j] = o[2][j] * inv2;
        Cb[(size_t)(r0 + 3) * HIDDEN + c0 + j] = o[3][j] * inv3;
    }
}

// ---------------------------------------------------------------------------
extern "C" void kernel_launch(void* const* d_in, const int* in_sizes, int n_in,
                              void* d_out, int out_size)
{
    const float* X    = (const float*)d_in[0];
    const float* mask = (const float*)d_in[1];
    const float* Wq   = (const float*)d_in[2];
    const float* bq   = (const float*)d_in[3];
    const float* Wk   = (const float*)d_in[4];
    const float* bk   = (const float*)d_in[5];
    const float* Wv   = (const float*)d_in[6];
    const float* bv   = (const float*)d_in[7];
    const float* Wo   = (const float*)d_in[8];
    const float* bo   = (const float*)d_in[9];
    float* out = (float*)d_out;

    float *gQ, *gK, *gV, *gC;
    cudaGetSymbolAddress((void**)&gQ, g_Q);
    cudaGetSymbolAddress((void**)&gK, g_K);
    cudaGetSymbolAddress((void**)&gV, g_V);
    cudaGetSymbolAddress((void**)&gC, g_C);

    cudaFuncSetAttribute(attn_kernel,
                         cudaFuncAttributeMaxDynamicSharedMemorySize,
                         ATTN_SMEM_BYTES);
    cudaFuncSetAttribute(gemm_mma_kernel,
                         cudaFuncAttributeMaxDynamicSharedMemorySize,
                         GEMM_SMEM_BYTES);

    dim3 ggrid(HIDDEN / 128, M_TOTAL / 128);   // (6, 64)
    gemm_mma_kernel<<<ggrid, 256, GEMM_SMEM_BYTES>>>(X, Wq, bq, gQ);
    gemm_mma_kernel<<<ggrid, 256, GEMM_SMEM_BYTES>>>(X, Wk, bk, gK);
    gemm_mma_kernel<<<ggrid, 256, GEMM_SMEM_BYTES>>>(X, Wv, bv, gV);

    dim3 agrid(S_LEN / 64, NH, B_SZ);          // (32, 12, 4)
    attn_kernel<<<agrid, 256, ATTN_SMEM_BYTES>>>(gQ, gK, gV, mask, gC);

    gemm_mma_kernel<<<ggrid, 256, GEMM_SMEM_BYTES>>>(gC, Wo, bo, out);
}

// round 4
// speedup vs baseline: 3.2554x; 2.4678x over previous
#include <cuda_runtime.h>
#include <cuda_bf16.h>
#include <cstdint>
#include <math.h>

#define HIDDEN 768
#define S_LEN  2048
#define B_SZ   4
#define NH     12
#define HD     64
#define M_TOTAL (B_SZ * S_LEN)   // 8192
#define GK 768

// Scratch (device globals: allocation-free per harness rules)
__device__ float g_Q[M_TOTAL * HIDDEN];
__device__ float g_K[M_TOTAL * HIDDEN];
__device__ float g_V[M_TOTAL * HIDDEN];
__device__ float g_C[M_TOTAL * HIDDEN];

// ===========================================================================
// Warp MMA helpers (base sm_103 PTX: ldmatrix + mma.sync, sm_80-era features)
// ===========================================================================
__device__ __forceinline__ uint32_t smem_u32(const void* p) {
    uint32_t a;
    asm("{ .reg .u64 t; cvta.to.shared.u64 t, %1; cvt.u32.u64 %0, t; }"
        : "=r"(a) : "l"(p));
    return a;
}

__device__ __forceinline__ void ldsm_x4(uint32_t addr, uint32_t* r) {
    asm volatile("ldmatrix.sync.aligned.m8n8.x4.shared.b16 {%0,%1,%2,%3}, [%4];"
        : "=r"(r[0]), "=r"(r[1]), "=r"(r[2]), "=r"(r[3]) : "r"(addr));
}

__device__ __forceinline__ void ldsm_x4_t(uint32_t addr, uint32_t* r) {
    asm volatile("ldmatrix.sync.aligned.m8n8.x4.trans.shared.b16 {%0,%1,%2,%3}, [%4];"
        : "=r"(r[0]), "=r"(r[1]), "=r"(r[2]), "=r"(r[3]) : "r"(addr));
}

__device__ __forceinline__ void mma_bf16(float* d, const uint32_t* a,
                                         uint32_t b0, uint32_t b1) {
    asm volatile(
        "mma.sync.aligned.m16n8k16.row.col.f32.bf16.bf16.f32 "
        "{%0,%1,%2,%3}, {%4,%5,%6,%7}, {%8,%9}, {%0,%1,%2,%3};"
        : "+f"(d[0]), "+f"(d[1]), "+f"(d[2]), "+f"(d[3])
        : "r"(a[0]), "r"(a[1]), "r"(a[2]), "r"(a[3]), "r"(b0), "r"(b1));
}

__device__ __forceinline__ void split4(float4 v, uint2& hi, uint2& lo) {
    __nv_bfloat162 h0 = __floats2bfloat162_rn(v.x, v.y);
    __nv_bfloat162 h1 = __floats2bfloat162_rn(v.z, v.w);
    __nv_bfloat162 l0 = __floats2bfloat162_rn(v.x - __bfloat162float(h0.x),
                                              v.y - __bfloat162float(h0.y));
    __nv_bfloat162 l1 = __floats2bfloat162_rn(v.z - __bfloat162float(h1.x),
                                              v.w - __bfloat162float(h1.y));
    hi.x = *(uint32_t*)&h0; hi.y = *(uint32_t*)&h1;
    lo.x = *(uint32_t*)&l0; lo.y = *(uint32_t*)&l1;
}

__device__ __forceinline__ uint32_t pack_split(float x, float y, uint32_t& lo) {
    __nv_bfloat162 h = __floats2bfloat162_rn(x, y);
    __nv_bfloat162 l = __floats2bfloat162_rn(x - __bfloat162float(h.x),
                                             y - __bfloat162float(h.y));
    lo = *(uint32_t*)&l;
    return *(uint32_t*)&h;
}

// ===========================================================================
// GEMM: C[M,N] = A[M,K] @ W[N,K]^T + bias (mma.sync bf16 split-precision)
// Unchanged from R3 (verified).
// ===========================================================================
#define BK 32
#define KSTEPS (GK / BK)
#define LDSTR 40
#define TILE_B (128 * LDSTR * 2)
#define STAGE_B (4 * TILE_B)
#define GEMM_SMEM_BYTES (2 * STAGE_B)

#define AH_O 0
#define AL_O TILE_B
#define WH_O (2 * TILE_B)
#define WL_O (3 * TILE_B)

__global__ __launch_bounds__(256, 1)
void gemm_mma_kernel(const float* __restrict__ A, const float* __restrict__ W,
                     const float* __restrict__ bias, float* __restrict__ C)
{
    extern __shared__ char smc[];
    const uint32_t sb = smem_u32(smc);
    const int tid  = threadIdx.x;
    const int lane = tid & 31;
    const int wid  = tid >> 5;
    const int bm = blockIdx.y * 128;
    const int bn = blockIdx.x * 128;
    const int wm = (wid & 1) * 64;
    const int wn = (wid >> 1) * 32;

    const int lr_row = tid >> 3;
    const int lr_k   = (tid & 7) * 4;

    float4 aV[4], wV[4];

    {
        const float* Ab = A + (size_t)bm * GK;
        const float* Wb = W + (size_t)bn * GK;
        #pragma unroll
        for (int rep = 0; rep < 4; rep++) {
            int row = rep * 32 + lr_row;
            aV[rep] = *(const float4*)(Ab + (size_t)row * GK + lr_k);
            wV[rep] = *(const float4*)(Wb + (size_t)row * GK + lr_k);
        }
        #pragma unroll
        for (int rep = 0; rep < 4; rep++) {
            int row = rep * 32 + lr_row;
            uint32_t off = (uint32_t)(row * (LDSTR * 2) + lr_k * 2);
            uint2 hi, lo;
            split4(aV[rep], hi, lo);
            *(uint2*)(smc + AH_O + off) = hi;
            *(uint2*)(smc + AL_O + off) = lo;
            split4(wV[rep], hi, lo);
            *(uint2*)(smc + WH_O + off) = hi;
            *(uint2*)(smc + WL_O + off) = lo;
        }
    }
    __syncthreads();

    float acc[4][4][4] = {};

    const int frag_r = lane & 15;
    const int frag_k = (lane >> 4) << 3;

    for (int s = 0; s < KSTEPS; s++) {
        if (s + 1 < KSTEPS) {
            const float* Ab = A + (size_t)bm * GK + (s + 1) * BK;
            const float* Wb = W + (size_t)bn * GK + (s + 1) * BK;
            #pragma unroll
            for (int rep = 0; rep < 4; rep++) {
                int row = rep * 32 + lr_row;
                aV[rep] = *(const float4*)(Ab + (size_t)row * GK + lr_k);
                wV[rep] = *(const float4*)(Wb + (size_t)row * GK + lr_k);
            }
        }

        const uint32_t stg = sb + (uint32_t)((s & 1) * STAGE_B);
        #pragma unroll
        for (int kk = 0; kk < 2; kk++) {
            const uint32_t kbyte = (uint32_t)((kk * 16 + frag_k) * 2);
            uint32_t ah[4][4], al[4][4], wh[2][4], wl[2][4];
            #pragma unroll
            for (int mi = 0; mi < 4; mi++) {
                uint32_t ro = (uint32_t)((wm + mi * 16 + frag_r) * (LDSTR * 2)) + kbyte;
                ldsm_x4(stg + AH_O + ro, ah[mi]);
                ldsm_x4(stg + AL_O + ro, al[mi]);
            }
            #pragma unroll
            for (int np = 0; np < 2; np++) {
                uint32_t ro = (uint32_t)((wn + np * 16 + frag_r) * (LDSTR * 2)) + kbyte;
                ldsm_x4(stg + WH_O + ro, wh[np]);
                ldsm_x4(stg + WL_O + ro, wl[np]);
            }
            #pragma unroll
            for (int mi = 0; mi < 4; mi++) {
                #pragma unroll
                for (int nj = 0; nj < 4; nj++) {
                    const int np = nj >> 1, sub = nj & 1;
                    uint32_t bh0 = wh[np][sub], bh1 = wh[np][sub + 2];
                    uint32_t bl0 = wl[np][sub], bl1 = wl[np][sub + 2];
                    mma_bf16(acc[mi][nj], ah[mi], bh0, bh1);
                    mma_bf16(acc[mi][nj], ah[mi], bl0, bl1);
                    mma_bf16(acc[mi][nj], al[mi], bh0, bh1);
                }
            }
        }
        __syncthreads();

        if (s + 1 < KSTEPS) {
            char* dst = smc + ((s + 1) & 1) * STAGE_B;
            #pragma unroll
            for (int rep = 0; rep < 4; rep++) {
                int row = rep * 32 + lr_row;
                uint32_t off = (uint32_t)(row * (LDSTR * 2) + lr_k * 2);
                uint2 hi, lo;
                split4(aV[rep], hi, lo);
                *(uint2*)(dst + AH_O + off) = hi;
                *(uint2*)(dst + AL_O + off) = lo;
                split4(wV[rep], hi, lo);
                *(uint2*)(dst + WH_O + off) = hi;
                *(uint2*)(dst + WL_O + off) = lo;
            }
            __syncthreads();
        }
    }

    const int gr = lane >> 2;
    const int cp = (lane & 3) * 2;
    #pragma unroll
    for (int mi = 0; mi < 4; mi++) {
        #pragma unroll
        for (int nj = 0; nj < 4; nj++) {
            int row0 = bm + wm + mi * 16 + gr;
            int col  = bn + wn + nj * 8 + cp;
            float b0 = bias[col], b1 = bias[col + 1];
            float2 v0 = { acc[mi][nj][0] + b0, acc[mi][nj][1] + b1 };
            float2 v1 = { acc[mi][nj][2] + b0, acc[mi][nj][3] + b1 };
            *(float2*)&C[(size_t)row0 * GK + col] = v0;
            *(float2*)&C[(size_t)(row0 + 8) * GK + col] = v1;
        }
    }
}

// ===========================================================================
// Flash attention via mma.sync bf16 split-precision.
// grid=(32,12,4), block=128 (4 warps). Warp = 16 query rows of a 64-q tile.
// smem: Q/K/V hi+lo tiles 64x64 bf16, row stride 72 elems (144B); bias[64].
// ===========================================================================
#define ASTR 144                        // bytes per smem row (72 bf16)
#define ATILE (64 * ASTR)               // 9216
#define AQH 0
#define AQL ATILE
#define AKH (2 * ATILE)
#define AKL (3 * ATILE)
#define AVH (4 * ATILE)
#define AVL (5 * ATILE)
#define ABI (6 * ATILE)
#define ATTN_SMEM_BYTES (ABI + 256)     // 55552

__device__ __forceinline__ void stage_tile64(const float* __restrict__ g,
                                             char* hi, char* lo,
                                             int tid, float scale)
{
    #pragma unroll
    for (int rep = 0; rep < 8; rep++) {
        int slot = rep * 128 + tid;       // 0..1023
        int row  = slot >> 4;             // 0..63
        int c4   = (slot & 15) * 4;       // 0..60
        float4 v = *(const float4*)(g + (size_t)row * HIDDEN + c4);
        v.x *= scale; v.y *= scale; v.z *= scale; v.w *= scale;
        uint2 h, l;
        split4(v, h, l);
        *(uint2*)(hi + row * ASTR + c4 * 2) = h;
        *(uint2*)(lo + row * ASTR + c4 * 2) = l;
    }
}

__global__ __launch_bounds__(128, 4)
void attn_mma_kernel(const float* __restrict__ Q, const float* __restrict__ K,
                     const float* __restrict__ V, const float* __restrict__ mask,
                     float* __restrict__ Ctx)
{
    extern __shared__ char smc[];
    const uint32_t sb = smem_u32(smc);
    float* Bi = (float*)(smc + ABI);

    const int b  = blockIdx.z;
    const int h  = blockIdx.y;
    const int qt = blockIdx.x;
    const int tid  = threadIdx.x;
    const int lane = tid & 31;
    const int wid  = tid >> 5;

    const int t  = lane & 3;
    const int gr = lane >> 2;
    const int frag_r = lane & 15;
    const int frag_k = (lane >> 4) << 3;
    // trans-ldmatrix lane addressing for V (B operand from [key][dim] layout)
    const int v_kr = (lane & 7) + ((lane >> 4) << 3);  // + kk*16
    const int v_nc = (lane & 8);                       // + np*16

    const float* Qg = Q + ((size_t)b * S_LEN + (size_t)qt * 64) * HIDDEN + h * HD;

    stage_tile64(Qg, smc + AQH, smc + AQL, tid, 0.125f);

    float o[8][4] = {};
    float m0 = -1e30f, m1 = -1e30f, l0 = 0.0f, l1 = 0.0f;

    for (int kt = 0; kt < S_LEN / 64; kt++) {
        __syncthreads();   // prev compute done (also covers Q staging on kt=0)
        const float* Kg = K + ((size_t)b * S_LEN + (size_t)kt * 64) * HIDDEN + h * HD;
        const float* Vg = V + ((size_t)b * S_LEN + (size_t)kt * 64) * HIDDEN + h * HD;
        stage_tile64(Kg, smc + AKH, smc + AKL, tid, 1.0f);
        stage_tile64(Vg, smc + AVH, smc + AVL, tid, 1.0f);
        if (tid < 64)
            Bi[tid] = (1.0f - mask[(size_t)b * S_LEN + kt * 64 + tid]) * -10000.0f;
        __syncthreads();

        // ---- S = Q K^T (3-term split)
        float s[8][4] = {};
        #pragma unroll
        for (int kk = 0; kk < 4; kk++) {
            const uint32_t kbyte = (uint32_t)((kk * 16 + frag_k) * 2);
            uint32_t ah[4], al[4];
            uint32_t qo = (uint32_t)((wid * 16 + frag_r) * ASTR) + kbyte;
            ldsm_x4(sb + AQH + qo, ah);
            ldsm_x4(sb + AQL + qo, al);
            #pragma unroll
            for (int np = 0; np < 4; np++) {
                uint32_t kh[4], kl[4];
                uint32_t ko = (uint32_t)((np * 16 + frag_r) * ASTR) + kbyte;
                ldsm_x4(sb + AKH + ko, kh);
                ldsm_x4(sb + AKL + ko, kl);
                #pragma unroll
                for (int sub = 0; sub < 2; sub++) {
                    int nj = np * 2 + sub;
                    mma_bf16(s[nj], ah, kh[sub], kh[sub + 2]);
                    mma_bf16(s[nj], ah, kl[sub], kl[sub + 2]);
                    mma_bf16(s[nj], al, kh[sub], kh[sub + 2]);
                }
            }
        }

        // ---- online softmax (registers)
        float m0n = -1e30f, m1n = -1e30f;
        #pragma unroll
        for (int nj = 0; nj < 8; nj++) {
            float b0 = Bi[nj * 8 + 2 * t];
            float b1 = Bi[nj * 8 + 2 * t + 1];
            s[nj][0] += b0; s[nj][1] += b1;
            s[nj][2] += b0; s[nj][3] += b1;
            m0n = fmaxf(m0n, fmaxf(s[nj][0], s[nj][1]));
            m1n = fmaxf(m1n, fmaxf(s[nj][2], s[nj][3]));
        }
        m0n = fmaxf(m0n, __shfl_xor_sync(0xffffffffu, m0n, 1));
        m0n = fmaxf(m0n, __shfl_xor_sync(0xffffffffu, m0n, 2));
        m1n = fmaxf(m1n, __shfl_xor_sync(0xffffffffu, m1n, 1));
        m1n = fmaxf(m1n, __shfl_xor_sync(0xffffffffu, m1n, 2));
        float m0w = fmaxf(m0, m0n);
        float m1w = fmaxf(m1, m1n);
        float a0 = __expf(m0 - m0w);
        float a1 = __expf(m1 - m1w);
        float sum0 = 0.0f, sum1 = 0.0f;
        #pragma unroll
        for (int nj = 0; nj < 8; nj++) {
            s[nj][0] = __expf(s[nj][0] - m0w);
            s[nj][1] = __expf(s[nj][1] - m0w);
            s[nj][2] = __expf(s[nj][2] - m1w);
            s[nj][3] = __expf(s[nj][3] - m1w);
            sum0 += s[nj][0] + s[nj][1];
            sum1 += s[nj][2] + s[nj][3];
        }
        l0 = l0 * a0 + sum0;
        l1 = l1 * a1 + sum1;
        m0 = m0w; m1 = m1w;
        #pragma unroll
        for (int nd = 0; nd < 8; nd++) {
            o[nd][0] *= a0; o[nd][1] *= a0;
            o[nd][2] *= a1; o[nd][3] *= a1;
        }

        // ---- O += P V (3-term split; P from regs, V via ldmatrix.trans)
        #pragma unroll
        for (int kk = 0; kk < 4; kk++) {
            const int j0 = 2 * kk, j1 = 2 * kk + 1;
            uint32_t ah[4], al[4];
            ah[0] = pack_split(s[j0][0], s[j0][1], al[0]);
            ah[1] = pack_split(s[j0][2], s[j0][3], al[1]);
            ah[2] = pack_split(s[j1][0], s[j1][1], al[2]);
            ah[3] = pack_split(s[j1][2], s[j1][3], al[3]);
            #pragma unroll
            for (int np = 0; np < 4; np++) {
                uint32_t vh[4], vl[4];
                uint32_t vo = (uint32_t)((kk * 16 + v_kr) * ASTR
                                         + (np * 16 + v_nc) * 2);
                ldsm_x4_t(sb + AVH + vo, vh);
                ldsm_x4_t(sb + AVL + vo, vl);
                #pragma unroll
                for (int sub = 0; sub < 2; sub++) {
                    int nd = np * 2 + sub;
                    mma_bf16(o[nd], ah, vh[sub], vh[sub + 2]);
                    mma_bf16(o[nd], ah, vl[sub], vl[sub + 2]);
                    mma_bf16(o[nd], al, vh[sub], vh[sub + 2]);
                }
            }
        }
    }

    // final l reduce over quad + write out
    l0 += __shfl_xor_sync(0xffffffffu, l0, 1);
    l0 += __shfl_xor_sync(0xffffffffu, l0, 2);
    l1 += __shfl_xor_sync(0xffffffffu, l1, 1);
    l1 += __shfl_xor_sync(0xffffffffu, l1, 2);
    float inv0 = 1.0f / l0;
    float inv1 = 1.0f / l1;

    const size_t row0 = (size_t)b * S_LEN + (size_t)qt * 64 + wid * 16 + gr;
    float* Cb = Ctx + row0 * HIDDEN + h * HD;
    #pragma unroll
    for (int nd = 0; nd < 8; nd++) {
        int col = nd * 8 + 2 * t;
        float2 v0 = { o[nd][0] * inv0, o[nd][1] * inv0 };
        float2 v1 = { o[nd][2] * inv1, o[nd][3] * inv1 };
        *(float2*)&Cb[col] = v0;
        *(float2*)&Cb[(size_t)8 * HIDDEN + col] = v1;
    }
}

// ---------------------------------------------------------------------------
extern "C" void kernel_launch(void* const* d_in, const int* in_sizes, int n_in,
                              void* d_out, int out_size)
{
    const float* X    = (const float*)d_in[0];
    const float* mask = (const float*)d_in[1];
    const float* Wq   = (const float*)d_in[2];
    const float* bq   = (const float*)d_in[3];
    const float* Wk   = (const float*)d_in[4];
    const float* bk   = (const float*)d_in[5];
    const float* Wv   = (const float*)d_in[6];
    const float* bv   = (const float*)d_in[7];
    const float* Wo   = (const float*)d_in[8];
    const float* bo   = (const float*)d_in[9];
    float* out = (float*)d_out;

    float *gQ, *gK, *gV, *gC;
    cudaGetSymbolAddress((void**)&gQ, g_Q);
    cudaGetSymbolAddress((void**)&gK, g_K);
    cudaGetSymbolAddress((void**)&gV, g_V);
    cudaGetSymbolAddress((void**)&gC, g_C);

    cudaFuncSetAttribute(gemm_mma_kernel,
                         cudaFuncAttributeMaxDynamicSharedMemorySize,
                         GEMM_SMEM_BYTES);
    cudaFuncSetAttribute(attn_mma_kernel,
                         cudaFuncAttributeMaxDynamicSharedMemorySize,
                         ATTN_SMEM_BYTES);

    dim3 ggrid(HIDDEN / 128, M_TOTAL / 128);   // (6, 64)
    gemm_mma_kernel<<<ggrid, 256, GEMM_SMEM_BYTES>>>(X, Wq, bq, gQ);
    gemm_mma_kernel<<<ggrid, 256, GEMM_SMEM_BYTES>>>(X, Wk, bk, gK);
    gemm_mma_kernel<<<ggrid, 256, GEMM_SMEM_BYTES>>>(X, Wv, bv, gV);

    dim3 agrid(S_LEN / 64, NH, B_SZ);          // (32, 12, 4)
    attn_mma_kernel<<<agrid, 128, ATTN_SMEM_BYTES>>>(gQ, gK, gV, mask, gC);

    gemm_mma_kernel<<<ggrid, 256, GEMM_SMEM_BYTES>>>(gC, Wo, bo, out);
}

// round 5
// speedup vs baseline: 3.3434x; 1.0270x over previous
#include <cuda_runtime.h>
#include <cuda_bf16.h>
#include <cstdint>
#include <math.h>

#define HIDDEN 768
#define S_LEN  2048
#define B_SZ   4
#define NH     12
#define HD     64
#define M_TOTAL (B_SZ * S_LEN)   // 8192
#define GK 768
#define LOG2E 1.4426950408889634f
#define SCALEQ (0.125f * LOG2E)

typedef __nv_bfloat16 bf16;

// Pre-split scratch (device globals: allocation-free per harness rules)
__device__ bf16 g_Xh[M_TOTAL * GK], g_Xl[M_TOTAL * GK];
__device__ bf16 g_Wh[4][GK * GK],  g_Wl[4][GK * GK];
__device__ bf16 g_Qh[M_TOTAL * GK], g_Ql[M_TOTAL * GK];
__device__ bf16 g_Kh[M_TOTAL * GK], g_Kl[M_TOTAL * GK];
__device__ bf16 g_Vh[M_TOTAL * GK], g_Vl[M_TOTAL * GK];
__device__ bf16 g_Ch[M_TOTAL * GK], g_Cl[M_TOTAL * GK];

// ===========================================================================
// Helpers
// ===========================================================================
__device__ __forceinline__ uint32_t smem_u32(const void* p) {
    uint32_t a;
    asm("{ .reg .u64 t; cvta.to.shared.u64 t, %1; cvt.u32.u64 %0, t; }"
        : "=r"(a) : "l"(p));
    return a;
}

__device__ __forceinline__ void ldsm_x4(uint32_t addr, uint32_t* r) {
    asm volatile("ldmatrix.sync.aligned.m8n8.x4.shared.b16 {%0,%1,%2,%3}, [%4];"
        : "=r"(r[0]), "=r"(r[1]), "=r"(r[2]), "=r"(r[3]) : "r"(addr));
}

__device__ __forceinline__ void ldsm_x4_t(uint32_t addr, uint32_t* r) {
    asm volatile("ldmatrix.sync.aligned.m8n8.x4.trans.shared.b16 {%0,%1,%2,%3}, [%4];"
        : "=r"(r[0]), "=r"(r[1]), "=r"(r[2]), "=r"(r[3]) : "r"(addr));
}

__device__ __forceinline__ void mma_bf16(float* d, const uint32_t* a,
                                         uint32_t b0, uint32_t b1) {
    asm volatile(
        "mma.sync.aligned.m16n8k16.row.col.f32.bf16.bf16.f32 "
        "{%0,%1,%2,%3}, {%4,%5,%6,%7}, {%8,%9}, {%0,%1,%2,%3};"
        : "+f"(d[0]), "+f"(d[1]), "+f"(d[2]), "+f"(d[3])
        : "r"(a[0]), "r"(a[1]), "r"(a[2]), "r"(a[3]), "r"(b0), "r"(b1));
}

__device__ __forceinline__ void split4(float4 v, uint2& hi, uint2& lo) {
    __nv_bfloat162 h0 = __floats2bfloat162_rn(v.x, v.y);
    __nv_bfloat162 h1 = __floats2bfloat162_rn(v.z, v.w);
    __nv_bfloat162 l0 = __floats2bfloat162_rn(v.x - __bfloat162float(h0.x),
                                              v.y - __bfloat162float(h0.y));
    __nv_bfloat162 l1 = __floats2bfloat162_rn(v.z - __bfloat162float(h1.x),
                                              v.w - __bfloat162float(h1.y));
    hi.x = *(uint32_t*)&h0; hi.y = *(uint32_t*)&h1;
    lo.x = *(uint32_t*)&l0; lo.y = *(uint32_t*)&l1;
}

__device__ __forceinline__ uint32_t pack_split(float x, float y, uint32_t& lo) {
    __nv_bfloat162 h = __floats2bfloat162_rn(x, y);
    __nv_bfloat162 l = __floats2bfloat162_rn(x - __bfloat162float(h.x),
                                             y - __bfloat162float(h.y));
    lo = *(uint32_t*)&l;
    return *(uint32_t*)&h;
}

__device__ __forceinline__ float ex2(float x) {
    float y;
    asm("ex2.approx.f32 %0, %1;" : "=f"(y) : "f"(x));
    return y;
}

__device__ __forceinline__ void cp16(uint32_t dst, const void* src) {
    asm volatile("cp.async.cg.shared.global [%0], [%1], 16;"
                 :: "r"(dst), "l"(src));
}
__device__ __forceinline__ void cp4(uint32_t dst, const void* src) {
    asm volatile("cp.async.ca.shared.global [%0], [%1], 4;"
                 :: "r"(dst), "l"(src));
}
#define CP_COMMIT() asm volatile("cp.async.commit_group;" ::: "memory")
#define CP_WAIT0()  asm volatile("cp.async.wait_group 0;" ::: "memory")

// ===========================================================================
// Split kernel: fp32 -> bf16 hi/lo
// ===========================================================================
__global__ void split_kernel(const float* __restrict__ src,
                             bf16* __restrict__ dh, bf16* __restrict__ dl,
                             int n4)
{
    int i = blockIdx.x * blockDim.x + threadIdx.x;
    if (i < n4) {
        float4 v = *(const float4*)(src + (size_t)i * 4);
        uint2 h, l;
        split4(v, h, l);
        *(uint2*)(dh + (size_t)i * 4) = h;
        *(uint2*)(dl + (size_t)i * 4) = l;
    }
}

// ===========================================================================
// GEMM: C = alpha*(A @ W^T + bias), A/W pre-split bf16 hi/lo.
// CTA 128x128, BK=32, 8 warps (64x32 each), cp.async double-buffered.
// Output: bf16 hi/lo (Ch/Cl) or fp32 (Cf).
// ===========================================================================
#define GSTR 80                     // bytes per smem row (32 bf16 + pad)
#define GTILE (128 * GSTR)          // 10240
#define GSTAGE (4 * GTILE)          // 40960
#define GEMM_SMEM_BYTES (2 * GSTAGE)

__global__ __launch_bounds__(256, 2)
void gemm_bf16_kernel(const bf16* __restrict__ Ah, const bf16* __restrict__ Al,
                      const bf16* __restrict__ Wh, const bf16* __restrict__ Wl,
                      const float* __restrict__ bias, float alpha,
                      bf16* __restrict__ Ch, bf16* __restrict__ Cl,
                      float* __restrict__ Cf)
{
    extern __shared__ char smc[];
    const uint32_t sb = smem_u32(smc);
    const int tid  = threadIdx.x;
    const int lane = tid & 31;
    const int wid  = tid >> 5;
    const int bm = blockIdx.y * 128;
    const int bn = blockIdx.x * 128;
    const int wm = (wid & 1) * 64;
    const int wn = (wid >> 1) * 32;

    const bf16* srcs[4] = { Ah + (size_t)bm * GK, Al + (size_t)bm * GK,
                            Wh + (size_t)bn * GK, Wl + (size_t)bn * GK };

    // stage issue: 4 parts x 128 rows x 64B (4x16B chunks)
    auto issue = [&](int s, int buf) {
        const uint32_t dbase = sb + (uint32_t)(buf * GSTAGE);
        #pragma unroll
        for (int p = 0; p < 4; p++) {
            const bf16* base = srcs[p] + s * 32;
            #pragma unroll
            for (int i = 0; i < 2; i++) {
                int idx = tid + i * 256;         // 0..511
                int row = idx >> 2, kc = idx & 3;
                cp16(dbase + (uint32_t)(p * GTILE + row * GSTR + kc * 16),
                     base + (size_t)row * GK + kc * 8);
            }
        }
    };

    issue(0, 0);
    CP_COMMIT();

    float acc[4][4][4] = {};
    const int frag_r = lane & 15;
    const int frag_k = (lane >> 4) << 3;

    #define KSTEPS24 24
    for (int s = 0; s < KSTEPS24; s++) {
        CP_WAIT0();
        __syncthreads();
        if (s + 1 < KSTEPS24) {
            issue(s + 1, (s + 1) & 1);
            CP_COMMIT();
        }
        const uint32_t stg = sb + (uint32_t)((s & 1) * GSTAGE);
        #pragma unroll
        for (int kk = 0; kk < 2; kk++) {
            const uint32_t kbyte = (uint32_t)((kk * 16 + frag_k) * 2);
            uint32_t ah[4][4], al[4][4], wh[2][4], wl[2][4];
            #pragma unroll
            for (int mi = 0; mi < 4; mi++) {
                uint32_t ro = (uint32_t)((wm + mi * 16 + frag_r) * GSTR) + kbyte;
                ldsm_x4(stg + 0 * GTILE + ro, ah[mi]);
                ldsm_x4(stg + 1 * GTILE + ro, al[mi]);
            }
            #pragma unroll
            for (int np = 0; np < 2; np++) {
                uint32_t ro = (uint32_t)((wn + np * 16 + frag_r) * GSTR) + kbyte;
                ldsm_x4(stg + 2 * GTILE + ro, wh[np]);
                ldsm_x4(stg + 3 * GTILE + ro, wl[np]);
            }
            #pragma unroll
            for (int mi = 0; mi < 4; mi++) {
                #pragma unroll
                for (int nj = 0; nj < 4; nj++) {
                    const int np = nj >> 1, sub = nj & 1;
                    uint32_t bh0 = wh[np][sub], bh1 = wh[np][sub + 2];
                    uint32_t bl0 = wl[np][sub], bl1 = wl[np][sub + 2];
                    mma_bf16(acc[mi][nj], ah[mi], bh0, bh1);
                    mma_bf16(acc[mi][nj], ah[mi], bl0, bl1);
                    mma_bf16(acc[mi][nj], al[mi], bh0, bh1);
                }
            }
        }
        __syncthreads();
    }

    // epilogue
    const int gr = lane >> 2;
    const int cp = (lane & 3) * 2;
    #pragma unroll
    for (int mi = 0; mi < 4; mi++) {
        #pragma unroll
        for (int nj = 0; nj < 4; nj++) {
            int row0 = bm + wm + mi * 16 + gr;
            int col  = bn + wn + nj * 8 + cp;
            float b0 = bias[col], b1 = bias[col + 1];
            float v00 = alpha * (acc[mi][nj][0] + b0);
            float v01 = alpha * (acc[mi][nj][1] + b1);
            float v10 = alpha * (acc[mi][nj][2] + b0);
            float v11 = alpha * (acc[mi][nj][3] + b1);
            if (Cf) {
                float2 f0 = { v00, v01 }, f1 = { v10, v11 };
                *(float2*)&Cf[(size_t)row0 * GK + col] = f0;
                *(float2*)&Cf[(size_t)(row0 + 8) * GK + col] = f1;
            } else {
                uint32_t l0, l1;
                uint32_t h0 = pack_split(v00, v01, l0);
                uint32_t h1 = pack_split(v10, v11, l1);
                *(uint32_t*)&Ch[(size_t)row0 * GK + col] = h0;
                *(uint32_t*)&Cl[(size_t)row0 * GK + col] = l0;
                *(uint32_t*)&Ch[(size_t)(row0 + 8) * GK + col] = h1;
                *(uint32_t*)&Cl[(size_t)(row0 + 8) * GK + col] = l1;
            }
        }
    }
}

// ===========================================================================
// Flash attention, pre-split bf16 inputs, cp.async double-buffered K/V.
// grid=(16,12,4), block=256 (8 warps). q-tile 128, k-tile 64.
// Q pre-scaled by 0.125*log2e (folded into Q-GEMM epilogue); softmax in exp2.
// ===========================================================================
#define ASTR 144                    // bytes per smem row (64 bf16 + pad)
#define AQH_O 0
#define AQL_O (128 * ASTR)          // 18432
#define ASTG0 (2 * 128 * ASTR)      // 36864
#define AKH_O 0
#define AKL_O (64 * ASTR)           // 9216
#define AVH_O (2 * 64 * ASTR)
#define AVL_O (3 * 64 * ASTR)
#define AMSK_O (4 * 64 * ASTR)      // 36864
#define ASTG_SZ (AMSK_O + 256)      // 37120
#define ATTN_SMEM_BYTES (ASTG0 + 2 * ASTG_SZ)   // 111104

__global__ __launch_bounds__(256, 2)
void attn_bf16_kernel(const bf16* __restrict__ Qh, const bf16* __restrict__ Ql,
                      const bf16* __restrict__ Kh, const bf16* __restrict__ Kl,
                      const bf16* __restrict__ Vh, const bf16* __restrict__ Vl,
                      const float* __restrict__ mask,
                      bf16* __restrict__ Ch, bf16* __restrict__ Cl)
{
    extern __shared__ char smc[];
    const uint32_t sb = smem_u32(smc);
    const int b  = blockIdx.z;
    const int h  = blockIdx.y;
    const int qt = blockIdx.x;
    const int tid  = threadIdx.x;
    const int lane = tid & 31;
    const int wid  = tid >> 5;

    const int t  = lane & 3;
    const int gr = lane >> 2;
    const int frag_r = lane & 15;
    const int frag_k = (lane >> 4) << 3;
    const int v_kr = (lane & 7) + ((lane >> 4) << 3);
    const int v_nc = (lane & 8);

    const size_t qbase = ((size_t)b * S_LEN + (size_t)qt * 128) * GK + h * HD;

    // stage K/V/mask tile kt into buffer
    auto issue_stage = [&](int kt, int buf) {
        const uint32_t dbase = sb + (uint32_t)(ASTG0 + buf * ASTG_SZ);
        const size_t off = ((size_t)b * S_LEN + (size_t)kt * 64) * GK + h * HD;
        const bf16* bases[4] = { Kh + off, Kl + off, Vh + off, Vl + off };
        #pragma unroll
        for (int p = 0; p < 4; p++) {
            #pragma unroll
            for (int i = 0; i < 2; i++) {
                int idx = tid + i * 256;       // 0..511
                int row = idx >> 3, kc = idx & 7;
                cp16(dbase + (uint32_t)(p * (64 * ASTR) + row * ASTR + kc * 16),
                     bases[p] + (size_t)row * GK + kc * 8);
            }
        }
        if (tid < 64)
            cp4(dbase + (uint32_t)(AMSK_O + tid * 4),
                mask + (size_t)b * S_LEN + kt * 64 + tid);
    };

    // prologue: Q tiles + stage 0
    {
        #pragma unroll
        for (int i = 0; i < 4; i++) {
            int idx = tid + i * 256;           // 0..1023
            int row = idx >> 3, kc = idx & 7;
            cp16(sb + (uint32_t)(AQH_O + row * ASTR + kc * 16),
                 Qh + qbase + (size_t)row * GK + kc * 8);
            cp16(sb + (uint32_t)(AQL_O + row * ASTR + kc * 16),
                 Ql + qbase + (size_t)row * GK + kc * 8);
        }
        issue_stage(0, 0);
        CP_COMMIT();
    }

    float o[8][4] = {};
    float m0 = -1e30f, m1 = -1e30f, l0 = 0.0f, l1 = 0.0f;

    for (int kt = 0; kt < S_LEN / 64; kt++) {
        CP_WAIT0();
        __syncthreads();
        if (kt + 1 < S_LEN / 64) {
            issue_stage(kt + 1, (kt + 1) & 1);
            CP_COMMIT();
        }
        const uint32_t stg = sb + (uint32_t)(ASTG0 + (kt & 1) * ASTG_SZ);
        const float* Ms = (const float*)(smc + ASTG0 + (kt & 1) * ASTG_SZ + AMSK_O);

        // ---- S = Q K^T (3-term split)
        float s[8][4] = {};
        #pragma unroll
        for (int kk = 0; kk < 4; kk++) {
            const uint32_t kbyte = (uint32_t)((kk * 16 + frag_k) * 2);
            uint32_t ah[4], al[4];
            uint32_t qo = (uint32_t)((wid * 16 + frag_r) * ASTR) + kbyte;
            ldsm_x4(sb + AQH_O + qo, ah);
            ldsm_x4(sb + AQL_O + qo, al);
            #pragma unroll
            for (int np = 0; np < 4; np++) {
                uint32_t kh[4], kl[4];
                uint32_t ko = (uint32_t)((np * 16 + frag_r) * ASTR) + kbyte;
                ldsm_x4(stg + AKH_O + ko, kh);
                ldsm_x4(stg + AKL_O + ko, kl);
                #pragma unroll
                for (int sub = 0; sub < 2; sub++) {
                    int nj = np * 2 + sub;
                    mma_bf16(s[nj], ah, kh[sub], kh[sub + 2]);
                    mma_bf16(s[nj], ah, kl[sub], kl[sub + 2]);
                    mma_bf16(s[nj], al, kh[sub], kh[sub + 2]);
                }
            }
        }

        // ---- online softmax (exp2 domain)
        float m0n = -1e30f, m1n = -1e30f;
        #pragma unroll
        for (int nj = 0; nj < 8; nj++) {
            float b0 = (1.0f - Ms[nj * 8 + 2 * t]) * (-10000.0f * LOG2E);
            float b1 = (1.0f - Ms[nj * 8 + 2 * t + 1]) * (-10000.0f * LOG2E);
            s[nj][0] += b0; s[nj][1] += b1;
            s[nj][2] += b0; s[nj][3] += b1;
            m0n = fmaxf(m0n, fmaxf(s[nj][0], s[nj][1]));
            m1n = fmaxf(m1n, fmaxf(s[nj][2], s[nj][3]));
        }
        m0n = fmaxf(m0n, __shfl_xor_sync(0xffffffffu, m0n, 1));
        m0n = fmaxf(m0n, __shfl_xor_sync(0xffffffffu, m0n, 2));
        m1n = fmaxf(m1n, __shfl_xor_sync(0xffffffffu, m1n, 1));
        m1n = fmaxf(m1n, __shfl_xor_sync(0xffffffffu, m1n, 2));
        float m0w = fmaxf(m0, m0n);
        float m1w = fmaxf(m1, m1n);
        float a0 = ex2(m0 - m0w);
        float a1 = ex2(m1 - m1w);
        float sum0 = 0.0f, sum1 = 0.0f;
        #pragma unroll
        for (int nj = 0; nj < 8; nj++) {
            s[nj][0] = ex2(s[nj][0] - m0w);
            s[nj][1] = ex2(s[nj][1] - m0w);
            s[nj][2] = ex2(s[nj][2] - m1w);
            s[nj][3] = ex2(s[nj][3] - m1w);
            sum0 += s[nj][0] + s[nj][1];
            sum1 += s[nj][2] + s[nj][3];
        }
        l0 = l0 * a0 + sum0;
        l1 = l1 * a1 + sum1;
        m0 = m0w; m1 = m1w;
        #pragma unroll
        for (int nd = 0; nd < 8; nd++) {
            o[nd][0] *= a0; o[nd][1] *= a0;
            o[nd][2] *= a1; o[nd][3] *= a1;
        }

        // ---- O += P V (3-term split; V via ldmatrix.trans)
        #pragma unroll
        for (int kk = 0; kk < 4; kk++) {
            const int j0 = 2 * kk, j1 = 2 * kk + 1;
            uint32_t ah[4], al[4];
            ah[0] = pack_split(s[j0][0], s[j0][1], al[0]);
            ah[1] = pack_split(s[j0][2], s[j0][3], al[1]);
            ah[2] = pack_split(s[j1][0], s[j1][1], al[2]);
            ah[3] = pack_split(s[j1][2], s[j1][3], al[3]);
            #pragma unroll
            for (int np = 0; np < 4; np++) {
                uint32_t vh[4], vl[4];
                uint32_t vo = (uint32_t)((kk * 16 + v_kr) * ASTR
                                         + (np * 16 + v_nc) * 2);
                ldsm_x4_t(stg + AVH_O + vo, vh);
                ldsm_x4_t(stg + AVL_O + vo, vl);
                #pragma unroll
                for (int sub = 0; sub < 2; sub++) {
                    int nd = np * 2 + sub;
                    mma_bf16(o[nd], ah, vh[sub], vh[sub + 2]);
                    mma_bf16(o[nd], ah, vl[sub], vl[sub + 2]);
                    mma_bf16(o[nd], al, vh[sub], vh[sub + 2]);
                }
            }
        }
        __syncthreads();
    }

    // final l reduce over quad + write out (pre-split bf16)
    l0 += __shfl_xor_sync(0xffffffffu, l0, 1);
    l0 += __shfl_xor_sync(0xffffffffu, l0, 2);
    l1 += __shfl_xor_sync(0xffffffffu, l1, 1);
    l1 += __shfl_xor_sync(0xffffffffu, l1, 2);
    float inv0 = 1.0f / l0;
    float inv1 = 1.0f / l1;

    const size_t row0 = (size_t)b * S_LEN + (size_t)qt * 128 + wid * 16 + gr;
    const size_t cb = row0 * GK + h * HD;
    #pragma unroll
    for (int nd = 0; nd < 8; nd++) {
        int col = nd * 8 + 2 * t;
        uint32_t lo0, lo1;
        uint32_t h0 = pack_split(o[nd][0] * inv0, o[nd][1] * inv0, lo0);
        uint32_t h1 = pack_split(o[nd][2] * inv1, o[nd][3] * inv1, lo1);
        *(uint32_t*)&Ch[cb + col] = h0;
        *(uint32_t*)&Cl[cb + col] = lo0;
        *(uint32_t*)&Ch[cb + (size_t)8 * GK + col] = h1;
        *(uint32_t*)&Cl[cb + (size_t)8 * GK + col] = lo1;
    }
}

// ---------------------------------------------------------------------------
extern "C" void kernel_launch(void* const* d_in, const int* in_sizes, int n_in,
                              void* d_out, int out_size)
{
    const float* X    = (const float*)d_in[0];
    const float* mask = (const float*)d_in[1];
    const float* Wq   = (const float*)d_in[2];
    const float* bq   = (const float*)d_in[3];
    const float* Wk   = (const float*)d_in[4];
    const float* bk   = (const float*)d_in[5];
    const float* Wv   = (const float*)d_in[6];
    const float* bv   = (const float*)d_in[7];
    const float* Wo   = (const float*)d_in[8];
    const float* bo   = (const float*)d_in[9];
    float* out = (float*)d_out;

    bf16 *xh, *xl, *wh, *wl, *qh, *ql, *kh, *kl, *vh, *vl, *ch, *cl;
    cudaGetSymbolAddress((void**)&xh, g_Xh);
    cudaGetSymbolAddress((void**)&xl, g_Xl);
    cudaGetSymbolAddress((void**)&wh, g_Wh);
    cudaGetSymbolAddress((void**)&wl, g_Wl);
    cudaGetSymbolAddress((void**)&qh, g_Qh);
    cudaGetSymbolAddress((void**)&ql, g_Ql);
    cudaGetSymbolAddress((void**)&kh, g_Kh);
    cudaGetSymbolAddress((void**)&kl, g_Kl);
    cudaGetSymbolAddress((void**)&vh, g_Vh);
    cudaGetSymbolAddress((void**)&vl, g_Vl);
    cudaGetSymbolAddress((void**)&ch, g_Ch);
    cudaGetSymbolAddress((void**)&cl, g_Cl);

    cudaFuncSetAttribute(gemm_bf16_kernel,
                         cudaFuncAttributeMaxDynamicSharedMemorySize,
                         GEMM_SMEM_BYTES);
    cudaFuncSetAttribute(attn_bf16_kernel,
                         cudaFuncAttributeMaxDynamicSharedMemorySize,
                         ATTN_SMEM_BYTES);

    // pre-split inputs
    split_kernel<<<(M_TOTAL * GK / 4 + 255) / 256, 256>>>(X, xh, xl, M_TOTAL * GK / 4);
    const int WN4 = GK * GK / 4;
    split_kernel<<<(WN4 + 255) / 256, 256>>>(Wq, wh + 0 * GK * GK, wl + 0 * GK * GK, WN4);
    split_kernel<<<(WN4 + 255) / 256, 256>>>(Wk, wh + 1 * GK * GK, wl + 1 * GK * GK, WN4);
    split_kernel<<<(WN4 + 255) / 256, 256>>>(Wv, wh + 2 * GK * GK, wl + 2 * GK * GK, WN4);
    split_kernel<<<(WN4 + 255) / 256, 256>>>(Wo, wh + 3 * GK * GK, wl + 3 * GK * GK, WN4);

    dim3 ggrid(GK / 128, M_TOTAL / 128);   // (6, 64)
    gemm_bf16_kernel<<<ggrid, 256, GEMM_SMEM_BYTES>>>(
        xh, xl, wh + 0 * GK * GK, wl + 0 * GK * GK, bq, SCALEQ, qh, ql, nullptr);
    gemm_bf16_kernel<<<ggrid, 256, GEMM_SMEM_BYTES>>>(
        xh, xl, wh + 1 * GK * GK, wl + 1 * GK * GK, bk, 1.0f, kh, kl, nullptr);
    gemm_bf16_kernel<<<ggrid, 256, GEMM_SMEM_BYTES>>>(
        xh, xl, wh + 2 * GK * GK, wl + 2 * GK * GK, bv, 1.0f, vh, vl, nullptr);

    dim3 agrid(S_LEN / 128, NH, B_SZ);     // (16, 12, 4)
    attn_bf16_kernel<<<agrid, 256, ATTN_SMEM_BYTES>>>(
        qh, ql, kh, kl, vh, vl, mask, ch, cl);

    gemm_bf16_kernel<<<ggrid, 256, GEMM_SMEM_BYTES>>>(
        ch, cl, wh + 3 * GK * GK, wl + 3 * GK * GK, bo, 1.0f, nullptr, nullptr, out);
}

// round 6
// speedup vs baseline: 3.4996x; 1.0467x over previous
#include <cuda_runtime.h>
#include <cuda_bf16.h>
#include <cstdint>
#include <math.h>

#define HIDDEN 768
#define S_LEN  2048
#define B_SZ   4
#define NH     12
#define HD     64
#define M_TOTAL (B_SZ * S_LEN)   // 8192
#define GK 768
#define LOG2E 1.4426950408889634f
#define SCALEQ (0.125f * LOG2E)

typedef __nv_bfloat16 bf16;

// Pre-split scratch (device globals: allocation-free per harness rules)
__device__ bf16 g_Xh[M_TOTAL * GK], g_Xl[M_TOTAL * GK];
__device__ bf16 g_Wh[4][GK * GK],  g_Wl[4][GK * GK];   // q,k,v contiguous; o at [3]
__device__ bf16 g_Qh[M_TOTAL * GK], g_Ql[M_TOTAL * GK];
__device__ bf16 g_Kh[M_TOTAL * GK], g_Kl[M_TOTAL * GK];
__device__ bf16 g_Vh[M_TOTAL * GK], g_Vl[M_TOTAL * GK];
__device__ bf16 g_Ch[M_TOTAL * GK], g_Cl[M_TOTAL * GK];
__device__ float g_bias3[3 * GK];

// ===========================================================================
// Helpers
// ===========================================================================
__device__ __forceinline__ uint32_t smem_u32(const void* p) {
    uint32_t a;
    asm("{ .reg .u64 t; cvta.to.shared.u64 t, %1; cvt.u32.u64 %0, t; }"
        : "=r"(a) : "l"(p));
    return a;
}

__device__ __forceinline__ void ldsm_x4(uint32_t addr, uint32_t* r) {
    asm volatile("ldmatrix.sync.aligned.m8n8.x4.shared.b16 {%0,%1,%2,%3}, [%4];"
        : "=r"(r[0]), "=r"(r[1]), "=r"(r[2]), "=r"(r[3]) : "r"(addr));
}

__device__ __forceinline__ void ldsm_x4_t(uint32_t addr, uint32_t* r) {
    asm volatile("ldmatrix.sync.aligned.m8n8.x4.trans.shared.b16 {%0,%1,%2,%3}, [%4];"
        : "=r"(r[0]), "=r"(r[1]), "=r"(r[2]), "=r"(r[3]) : "r"(addr));
}

__device__ __forceinline__ void mma_bf16(float* d, const uint32_t* a,
                                         uint32_t b0, uint32_t b1) {
    asm volatile(
        "mma.sync.aligned.m16n8k16.row.col.f32.bf16.bf16.f32 "
        "{%0,%1,%2,%3}, {%4,%5,%6,%7}, {%8,%9}, {%0,%1,%2,%3};"
        : "+f"(d[0]), "+f"(d[1]), "+f"(d[2]), "+f"(d[3])
        : "r"(a[0]), "r"(a[1]), "r"(a[2]), "r"(a[3]), "r"(b0), "r"(b1));
}

__device__ __forceinline__ void split4(float4 v, uint2& hi, uint2& lo) {
    __nv_bfloat162 h0 = __floats2bfloat162_rn(v.x, v.y);
    __nv_bfloat162 h1 = __floats2bfloat162_rn(v.z, v.w);
    __nv_bfloat162 l0 = __floats2bfloat162_rn(v.x - __bfloat162float(h0.x),
                                              v.y - __bfloat162float(h0.y));
    __nv_bfloat162 l1 = __floats2bfloat162_rn(v.z - __bfloat162float(h1.x),
                                              v.w - __bfloat162float(h1.y));
    hi.x = *(uint32_t*)&h0; hi.y = *(uint32_t*)&h1;
    lo.x = *(uint32_t*)&l0; lo.y = *(uint32_t*)&l1;
}

__device__ __forceinline__ uint32_t pack_split(float x, float y, uint32_t& lo) {
    __nv_bfloat162 h = __floats2bfloat162_rn(x, y);
    __nv_bfloat162 l = __floats2bfloat162_rn(x - __bfloat162float(h.x),
                                             y - __bfloat162float(h.y));
    lo = *(uint32_t*)&l;
    return *(uint32_t*)&h;
}

__device__ __forceinline__ float ex2(float x) {
    float y;
    asm("ex2.approx.f32 %0, %1;" : "=f"(y) : "f"(x));
    return y;
}

__device__ __forceinline__ void cp16(uint32_t dst, const void* src) {
    asm volatile("cp.async.cg.shared.global [%0], [%1], 16;"
                 :: "r"(dst), "l"(src));
}
__device__ __forceinline__ void cp4(uint32_t dst, const void* src) {
    asm volatile("cp.async.ca.shared.global [%0], [%1], 4;"
                 :: "r"(dst), "l"(src));
}
#define CP_COMMIT() asm volatile("cp.async.commit_group;" ::: "memory")
#define CP_WAIT0()  asm volatile("cp.async.wait_group 0;" ::: "memory")

// ===========================================================================
// Split kernel: fp32 -> bf16 hi/lo ; bias concat
// ===========================================================================
__global__ void split_kernel(const float* __restrict__ src,
                             bf16* __restrict__ dh, bf16* __restrict__ dl,
                             int n4)
{
    int i = blockIdx.x * blockDim.x + threadIdx.x;
    if (i < n4) {
        float4 v = *(const float4*)(src + (size_t)i * 4);
        uint2 h, l;
        split4(v, h, l);
        *(uint2*)(dh + (size_t)i * 4) = h;
        *(uint2*)(dl + (size_t)i * 4) = l;
    }
}

__global__ void concat_bias_kernel(const float* __restrict__ bq,
                                   const float* __restrict__ bk,
                                   const float* __restrict__ bv,
                                   float* __restrict__ dst)
{
    int i = blockIdx.x * blockDim.x + threadIdx.x;
    if (i < GK) dst[i] = bq[i];
    else if (i < 2 * GK) dst[i] = bk[i - GK];
    else if (i < 3 * GK) dst[i] = bv[i - 2 * GK];
}

// ===========================================================================
// GEMM: out = alpha*(A @ W^T + bias). A pre-split bf16 hi/lo, W pre-split.
// CTA 128x128, BK=32, 8 warps (64x32 each), cp.async double-buffered.
// N can span multiple 768-wide sections (fused QKV): output routed by section.
// If Cf != null: single-section fp32 output.
// ===========================================================================
#define GSTR 80
#define GTILE (128 * GSTR)
#define GSTAGE (4 * GTILE)
#define GEMM_SMEM_BYTES (2 * GSTAGE)

__global__ __launch_bounds__(256, 2)
void gemm_bf16_kernel(const bf16* __restrict__ Ah, const bf16* __restrict__ Al,
                      const bf16* __restrict__ Wh, const bf16* __restrict__ Wl,
                      const float* __restrict__ bias,
                      bf16* __restrict__ O0h, bf16* __restrict__ O0l,
                      bf16* __restrict__ O1h, bf16* __restrict__ O1l,
                      bf16* __restrict__ O2h, bf16* __restrict__ O2l,
                      float* __restrict__ Cf)
{
    extern __shared__ char smc[];
    const uint32_t sb = smem_u32(smc);
    const int tid  = threadIdx.x;
    const int lane = tid & 31;
    const int wid  = tid >> 5;
    const int bm = blockIdx.y * 128;
    const int bn = blockIdx.x * 128;
    const int wm = (wid & 1) * 64;
    const int wn = (wid >> 1) * 32;

    const int sec  = bn / GK;
    const int colb = bn - sec * GK;
    const float alpha = (Cf == nullptr && sec == 0) ? SCALEQ : 1.0f;
    bf16* Ho = (sec == 0) ? O0h : (sec == 1) ? O1h : O2h;
    bf16* Lo = (sec == 0) ? O0l : (sec == 1) ? O1l : O2l;

    const bf16* srcs[4] = { Ah + (size_t)bm * GK, Al + (size_t)bm * GK,
                            Wh + (size_t)bn * GK, Wl + (size_t)bn * GK };

    auto issue = [&](int s, int buf) {
        const uint32_t dbase = sb + (uint32_t)(buf * GSTAGE);
        #pragma unroll
        for (int p = 0; p < 4; p++) {
            const bf16* base = srcs[p] + s * 32;
            #pragma unroll
            for (int i = 0; i < 2; i++) {
                int idx = tid + i * 256;
                int row = idx >> 2, kc = idx & 3;
                cp16(dbase + (uint32_t)(p * GTILE + row * GSTR + kc * 16),
                     base + (size_t)row * GK + kc * 8);
            }
        }
    };

    issue(0, 0);
    CP_COMMIT();

    float acc[4][4][4] = {};
    const int frag_r = lane & 15;
    const int frag_k = (lane >> 4) << 3;

    #define KSTEPS24 24
    for (int s = 0; s < KSTEPS24; s++) {
        CP_WAIT0();
        __syncthreads();
        if (s + 1 < KSTEPS24) {
            issue(s + 1, (s + 1) & 1);
            CP_COMMIT();
        }
        const uint32_t stg = sb + (uint32_t)((s & 1) * GSTAGE);
        #pragma unroll
        for (int kk = 0; kk < 2; kk++) {
            const uint32_t kbyte = (uint32_t)((kk * 16 + frag_k) * 2);
            uint32_t ah[4][4], al[4][4], wh[2][4], wl[2][4];
            #pragma unroll
            for (int mi = 0; mi < 4; mi++) {
                uint32_t ro = (uint32_t)((wm + mi * 16 + frag_r) * GSTR) + kbyte;
                ldsm_x4(stg + 0 * GTILE + ro, ah[mi]);
                ldsm_x4(stg + 1 * GTILE + ro, al[mi]);
            }
            #pragma unroll
            for (int np = 0; np < 2; np++) {
                uint32_t ro = (uint32_t)((wn + np * 16 + frag_r) * GSTR) + kbyte;
                ldsm_x4(stg + 2 * GTILE + ro, wh[np]);
                ldsm_x4(stg + 3 * GTILE + ro, wl[np]);
            }
            #pragma unroll
            for (int mi = 0; mi < 4; mi++) {
                #pragma unroll
                for (int nj = 0; nj < 4; nj++) {
                    const int np = nj >> 1, sub = nj & 1;
                    uint32_t bh0 = wh[np][sub], bh1 = wh[np][sub + 2];
                    uint32_t bl0 = wl[np][sub], bl1 = wl[np][sub + 2];
                    mma_bf16(acc[mi][nj], ah[mi], bh0, bh1);
                    mma_bf16(acc[mi][nj], ah[mi], bl0, bl1);
                    mma_bf16(acc[mi][nj], al[mi], bh0, bh1);
                }
            }
        }
        __syncthreads();
    }

    const int gr = lane >> 2;
    const int cp = (lane & 3) * 2;
    #pragma unroll
    for (int mi = 0; mi < 4; mi++) {
        #pragma unroll
        for (int nj = 0; nj < 4; nj++) {
            int row0 = bm + wm + mi * 16 + gr;
            int colg = colb + wn + nj * 8 + cp;          // within-section col
            int bcol = bn + wn + nj * 8 + cp;            // bias index (global)
            float b0 = bias[bcol], b1 = bias[bcol + 1];
            float v00 = alpha * (acc[mi][nj][0] + b0);
            float v01 = alpha * (acc[mi][nj][1] + b1);
            float v10 = alpha * (acc[mi][nj][2] + b0);
            float v11 = alpha * (acc[mi][nj][3] + b1);
            if (Cf) {
                float2 f0 = { v00, v01 }, f1 = { v10, v11 };
                *(float2*)&Cf[(size_t)row0 * GK + colg] = f0;
                *(float2*)&Cf[(size_t)(row0 + 8) * GK + colg] = f1;
            } else {
                uint32_t l0, l1;
                uint32_t h0 = pack_split(v00, v01, l0);
                uint32_t h1 = pack_split(v10, v11, l1);
                *(uint32_t*)&Ho[(size_t)row0 * GK + colg] = h0;
                *(uint32_t*)&Lo[(size_t)row0 * GK + colg] = l0;
                *(uint32_t*)&Ho[(size_t)(row0 + 8) * GK + colg] = h1;
                *(uint32_t*)&Lo[(size_t)(row0 + 8) * GK + colg] = l1;
            }
        }
    }
}

// ===========================================================================
// Flash attention, 4 warps x 32 q-rows (mi=2) = 128-q tile, k-tile 64.
// Same smem layout as before; K/V ldsm amortized over 2x the q-rows.
// ===========================================================================
#define ASTR 144
#define AQH_O 0
#define AQL_O (128 * ASTR)
#define ASTG0 (2 * 128 * ASTR)
#define AKH_O 0
#define AKL_O (64 * ASTR)
#define AVH_O (2 * 64 * ASTR)
#define AVL_O (3 * 64 * ASTR)
#define AMSK_O (4 * 64 * ASTR)
#define ASTG_SZ (AMSK_O + 256)
#define ATTN_SMEM_BYTES (ASTG0 + 2 * ASTG_SZ)   // 111104

__global__ __launch_bounds__(128, 2)
void attn_bf16_kernel(const bf16* __restrict__ Qh, const bf16* __restrict__ Ql,
                      const bf16* __restrict__ Kh, const bf16* __restrict__ Kl,
                      const bf16* __restrict__ Vh, const bf16* __restrict__ Vl,
                      const float* __restrict__ mask,
                      bf16* __restrict__ Ch, bf16* __restrict__ Cl)
{
    extern __shared__ char smc[];
    const uint32_t sb = smem_u32(smc);
    const int b  = blockIdx.z;
    const int h  = blockIdx.y;
    const int qt = blockIdx.x;
    const int tid  = threadIdx.x;
    const int lane = tid & 31;
    const int wid  = tid >> 5;        // 0..3

    const int t  = lane & 3;
    const int gr = lane >> 2;
    const int frag_r = lane & 15;
    const int frag_k = (lane >> 4) << 3;
    const int v_kr = (lane & 7) + ((lane >> 4) << 3);
    const int v_nc = (lane & 8);

    const size_t qbase = ((size_t)b * S_LEN + (size_t)qt * 128) * GK + h * HD;

    auto issue_stage = [&](int kt, int buf) {
        const uint32_t dbase = sb + (uint32_t)(ASTG0 + buf * ASTG_SZ);
        const size_t off = ((size_t)b * S_LEN + (size_t)kt * 64) * GK + h * HD;
        const bf16* bases[4] = { Kh + off, Kl + off, Vh + off, Vl + off };
        #pragma unroll
        for (int p = 0; p < 4; p++) {
            #pragma unroll
            for (int i = 0; i < 4; i++) {
                int idx = tid + i * 128;       // 0..511
                int row = idx >> 3, kc = idx & 7;
                cp16(dbase + (uint32_t)(p * (64 * ASTR) + row * ASTR + kc * 16),
                     bases[p] + (size_t)row * GK + kc * 8);
            }
        }
        if (tid < 64)
            cp4(dbase + (uint32_t)(AMSK_O + tid * 4),
                mask + (size_t)b * S_LEN + kt * 64 + tid);
    };

    // prologue: Q tiles + stage 0
    {
        #pragma unroll
        for (int i = 0; i < 8; i++) {
            int idx = tid + i * 128;           // 0..1023
            int row = idx >> 3, kc = idx & 7;
            cp16(sb + (uint32_t)(AQH_O + row * ASTR + kc * 16),
                 Qh + qbase + (size_t)row * GK + kc * 8);
            cp16(sb + (uint32_t)(AQL_O + row * ASTR + kc * 16),
                 Ql + qbase + (size_t)row * GK + kc * 8);
        }
        issue_stage(0, 0);
        CP_COMMIT();
    }

    float o[2][8][4] = {};
    float m[2][2] = { { -1e30f, -1e30f }, { -1e30f, -1e30f } };
    float l[2][2] = {};

    for (int kt = 0; kt < S_LEN / 64; kt++) {
        CP_WAIT0();
        __syncthreads();
        if (kt + 1 < S_LEN / 64) {
            issue_stage(kt + 1, (kt + 1) & 1);
            CP_COMMIT();
        }
        const uint32_t stg = sb + (uint32_t)(ASTG0 + (kt & 1) * ASTG_SZ);
        const float* Ms = (const float*)(smc + ASTG0 + (kt & 1) * ASTG_SZ + AMSK_O);

        // ---- S = Q K^T (3-term split), mi = 2 blocks of 16 q rows
        float s[2][8][4] = {};
        #pragma unroll
        for (int kk = 0; kk < 4; kk++) {
            const uint32_t kbyte = (uint32_t)((kk * 16 + frag_k) * 2);
            uint32_t ah[2][4], al[2][4];
            #pragma unroll
            for (int mi = 0; mi < 2; mi++) {
                uint32_t qo = (uint32_t)((wid * 32 + mi * 16 + frag_r) * ASTR) + kbyte;
                ldsm_x4(sb + AQH_O + qo, ah[mi]);
                ldsm_x4(sb + AQL_O + qo, al[mi]);
            }
            #pragma unroll
            for (int np = 0; np < 4; np++) {
                uint32_t kh[4], kl[4];
                uint32_t ko = (uint32_t)((np * 16 + frag_r) * ASTR) + kbyte;
                ldsm_x4(stg + AKH_O + ko, kh);
                ldsm_x4(stg + AKL_O + ko, kl);
                #pragma unroll
                for (int sub = 0; sub < 2; sub++) {
                    int nj = np * 2 + sub;
                    uint32_t b0 = kh[sub], b1 = kh[sub + 2];
                    uint32_t c0 = kl[sub], c1 = kl[sub + 2];
                    #pragma unroll
                    for (int mi = 0; mi < 2; mi++) {
                        mma_bf16(s[mi][nj], ah[mi], b0, b1);
                        mma_bf16(s[mi][nj], ah[mi], c0, c1);
                        mma_bf16(s[mi][nj], al[mi], b0, b1);
                    }
                }
            }
        }

        // ---- online softmax (exp2 domain)
        float bb0[8], bb1[8];
        #pragma unroll
        for (int nj = 0; nj < 8; nj++) {
            bb0[nj] = (1.0f - Ms[nj * 8 + 2 * t]) * (-10000.0f * LOG2E);
            bb1[nj] = (1.0f - Ms[nj * 8 + 2 * t + 1]) * (-10000.0f * LOG2E);
        }
        #pragma unroll
        for (int mi = 0; mi < 2; mi++) {
            float m0n = -1e30f, m1n = -1e30f;
            #pragma unroll
            for (int nj = 0; nj < 8; nj++) {
                s[mi][nj][0] += bb0[nj]; s[mi][nj][1] += bb1[nj];
                s[mi][nj][2] += bb0[nj]; s[mi][nj][3] += bb1[nj];
                m0n = fmaxf(m0n, fmaxf(s[mi][nj][0], s[mi][nj][1]));
                m1n = fmaxf(m1n, fmaxf(s[mi][nj][2], s[mi][nj][3]));
            }
            m0n = fmaxf(m0n, __shfl_xor_sync(0xffffffffu, m0n, 1));
            m0n = fmaxf(m0n, __shfl_xor_sync(0xffffffffu, m0n, 2));
            m1n = fmaxf(m1n, __shfl_xor_sync(0xffffffffu, m1n, 1));
            m1n = fmaxf(m1n, __shfl_xor_sync(0xffffffffu, m1n, 2));
            float m0w = fmaxf(m[mi][0], m0n);
            float m1w = fmaxf(m[mi][1], m1n);
            float a0 = ex2(m[mi][0] - m0w);
            float a1 = ex2(m[mi][1] - m1w);
            float sum0 = 0.0f, sum1 = 0.0f;
            #pragma unroll
            for (int nj = 0; nj < 8; nj++) {
                s[mi][nj][0] = ex2(s[mi][nj][0] - m0w);
                s[mi][nj][1] = ex2(s[mi][nj][1] - m0w);
                s[mi][nj][2] = ex2(s[mi][nj][2] - m1w);
                s[mi][nj][3] = ex2(s[mi][nj][3] - m1w);
                sum0 += s[mi][nj][0] + s[mi][nj][1];
                sum1 += s[mi][nj][2] + s[mi][nj][3];
            }
            l[mi][0] = l[mi][0] * a0 + sum0;
            l[mi][1] = l[mi][1] * a1 + sum1;
            m[mi][0] = m0w; m[mi][1] = m1w;
            #pragma unroll
            for (int nd = 0; nd < 8; nd++) {
                o[mi][nd][0] *= a0; o[mi][nd][1] *= a0;
                o[mi][nd][2] *= a1; o[mi][nd][3] *= a1;
            }
        }

        // ---- O += P V (3-term split; V via ldmatrix.trans)
        #pragma unroll
        for (int kk = 0; kk < 4; kk++) {
            const int j0 = 2 * kk, j1 = 2 * kk + 1;
            uint32_t pah[2][4], pal[2][4];
            #pragma unroll
            for (int mi = 0; mi < 2; mi++) {
                pah[mi][0] = pack_split(s[mi][j0][0], s[mi][j0][1], pal[mi][0]);
                pah[mi][1] = pack_split(s[mi][j0][2], s[mi][j0][3], pal[mi][1]);
                pah[mi][2] = pack_split(s[mi][j1][0], s[mi][j1][1], pal[mi][2]);
                pah[mi][3] = pack_split(s[mi][j1][2], s[mi][j1][3], pal[mi][3]);
            }
            #pragma unroll
            for (int np = 0; np < 4; np++) {
                uint32_t vh[4], vl[4];
                uint32_t vo = (uint32_t)((kk * 16 + v_kr) * ASTR
                                         + (np * 16 + v_nc) * 2);
                ldsm_x4_t(stg + AVH_O + vo, vh);
                ldsm_x4_t(stg + AVL_O + vo, vl);
                #pragma unroll
                for (int sub = 0; sub < 2; sub++) {
                    int nd = np * 2 + sub;
                    uint32_t b0 = vh[sub], b1 = vh[sub + 2];
                    uint32_t c0 = vl[sub], c1 = vl[sub + 2];
                    #pragma unroll
                    for (int mi = 0; mi < 2; mi++) {
                        mma_bf16(o[mi][nd], pah[mi], b0, b1);
                        mma_bf16(o[mi][nd], pah[mi], c0, c1);
                        mma_bf16(o[mi][nd], pal[mi], b0, b1);
                    }
                }
            }
        }
        __syncthreads();
    }

    // final l reduce + write out (pre-split bf16)
    #pragma unroll
    for (int mi = 0; mi < 2; mi++) {
        float l0 = l[mi][0], l1 = l[mi][1];
        l0 += __shfl_xor_sync(0xffffffffu, l0, 1);
        l0 += __shfl_xor_sync(0xffffffffu, l0, 2);
        l1 += __shfl_xor_sync(0xffffffffu, l1, 1);
        l1 += __shfl_xor_sync(0xffffffffu, l1, 2);
        float inv0 = 1.0f / l0;
        float inv1 = 1.0f / l1;

        const size_t row0 = (size_t)b * S_LEN + (size_t)qt * 128
                          + wid * 32 + mi * 16 + gr;
        const size_t cb = row0 * GK + h * HD;
        #pragma unroll
        for (int nd = 0; nd < 8; nd++) {
            int col = nd * 8 + 2 * t;
            uint32_t lo0, lo1;
            uint32_t h0 = pack_split(o[mi][nd][0] * inv0, o[mi][nd][1] * inv0, lo0);
            uint32_t h1 = pack_split(o[mi][nd][2] * inv1, o[mi][nd][3] * inv1, lo1);
            *(uint32_t*)&Ch[cb + col] = h0;
            *(uint32_t*)&Cl[cb + col] = lo0;
            *(uint32_t*)&Ch[cb + (size_t)8 * GK + col] = h1;
            *(uint32_t*)&Cl[cb + (size_t)8 * GK + col] = lo1;
        }
    }
}

// ---------------------------------------------------------------------------
extern "C" void kernel_launch(void* const* d_in, const int* in_sizes, int n_in,
                              void* d_out, int out_size)
{
    const float* X    = (const float*)d_in[0];
    const float* mask = (const float*)d_in[1];
    const float* Wq   = (const float*)d_in[2];
    const float* bq   = (const float*)d_in[3];
    const float* Wk   = (const float*)d_in[4];
    const float* bk   = (const float*)d_in[5];
    const float* Wv   = (const float*)d_in[6];
    const float* bv   = (const float*)d_in[7];
    const float* Wo   = (const float*)d_in[8];
    const float* bo   = (const float*)d_in[9];
    float* out = (float*)d_out;

    bf16 *xh, *xl, *wh, *wl, *qh, *ql, *kh, *kl, *vh, *vl, *ch, *cl;
    float* b3;
    cudaGetSymbolAddress((void**)&xh, g_Xh);
    cudaGetSymbolAddress((void**)&xl, g_Xl);
    cudaGetSymbolAddress((void**)&wh, g_Wh);
    cudaGetSymbolAddress((void**)&wl, g_Wl);
    cudaGetSymbolAddress((void**)&qh, g_Qh);
    cudaGetSymbolAddress((void**)&ql, g_Ql);
    cudaGetSymbolAddress((void**)&kh, g_Kh);
    cudaGetSymbolAddress((void**)&kl, g_Kl);
    cudaGetSymbolAddress((void**)&vh, g_Vh);
    cudaGetSymbolAddress((void**)&vl, g_Vl);
    cudaGetSymbolAddress((void**)&ch, g_Ch);
    cudaGetSymbolAddress((void**)&cl, g_Cl);
    cudaGetSymbolAddress((void**)&b3, g_bias3);

    cudaFuncSetAttribute(gemm_bf16_kernel,
                         cudaFuncAttributeMaxDynamicSharedMemorySize,
                         GEMM_SMEM_BYTES);
    cudaFuncSetAttribute(attn_bf16_kernel,
                         cudaFuncAttributeMaxDynamicSharedMemorySize,
                         ATTN_SMEM_BYTES);

    // pre-split inputs + bias concat
    split_kernel<<<(M_TOTAL * GK / 4 + 255) / 256, 256>>>(X, xh, xl, M_TOTAL * GK / 4);
    const int WN4 = GK * GK / 4;
    split_kernel<<<(WN4 + 255) / 256, 256>>>(Wq, wh + 0 * GK * GK, wl + 0 * GK * GK, WN4);
    split_kernel<<<(WN4 + 255) / 256, 256>>>(Wk, wh + 1 * GK * GK, wl + 1 * GK * GK, WN4);
    split_kernel<<<(WN4 + 255) / 256, 256>>>(Wv, wh + 2 * GK * GK, wl + 2 * GK * GK, WN4);
    split_kernel<<<(WN4 + 255) / 256, 256>>>(Wo, wh + 3 * GK * GK, wl + 3 * GK * GK, WN4);
    concat_bias_kernel<<<(3 * GK + 255) / 256, 256>>>(bq, bk, bv, b3);

    // fused QKV projection: N = 2304
    dim3 fgrid(3 * GK / 128, M_TOTAL / 128);   // (18, 64)
    gemm_bf16_kernel<<<fgrid, 256, GEMM_SMEM_BYTES>>>(
        xh, xl, wh, wl, b3, qh, ql, kh, kl, vh, vl, nullptr);

    dim3 agrid(S_LEN / 128, NH, B_SZ);         // (16, 12, 4)
    attn_bf16_kernel<<<agrid, 128, ATTN_SMEM_BYTES>>>(
        qh, ql, kh, kl, vh, vl, mask, ch, cl);

    // output projection (fp32 out)
    dim3 ogrid(GK / 128, M_TOTAL / 128);       // (6, 64)
    gemm_bf16_kernel<<<ogrid, 256, GEMM_SMEM_BYTES>>>(
        ch, cl, wh + 3 * GK * GK, wl + 3 * GK * GK, bo,
        nullptr, nullptr, nullptr, nullptr, nullptr, nullptr, out);
}

// round 7
// speedup vs baseline: 3.5388x; 1.0112x over previous
#include <cuda_runtime.h>
#include <cuda_bf16.h>
#include <cstdint>
#include <math.h>

#define HIDDEN 768
#define S_LEN  2048
#define B_SZ   4
#define NH     12
#define HD     64
#define M_TOTAL (B_SZ * S_LEN)   // 8192
#define GK 768
#define LOG2E 1.4426950408889634f
#define SCALEQ (0.125f * LOG2E)

typedef __nv_bfloat16 bf16;

// Pre-split scratch (device globals: allocation-free per harness rules)
__device__ bf16 g_Xh[M_TOTAL * GK], g_Xl[M_TOTAL * GK];
__device__ bf16 g_Wh[4][GK * GK],  g_Wl[4][GK * GK];   // q,k,v contiguous; o at [3]
__device__ bf16 g_Qh[M_TOTAL * GK], g_Ql[M_TOTAL * GK];
__device__ bf16 g_Kh[M_TOTAL * GK], g_Kl[M_TOTAL * GK];
__device__ bf16 g_Vh[M_TOTAL * GK], g_Vl[M_TOTAL * GK];
__device__ bf16 g_Ch[M_TOTAL * GK], g_Cl[M_TOTAL * GK];
__device__ float g_bias3[3 * GK];

// ===========================================================================
// Helpers
// ===========================================================================
__device__ __forceinline__ uint32_t smem_u32(const void* p) {
    uint32_t a;
    asm("{ .reg .u64 t; cvta.to.shared.u64 t, %1; cvt.u32.u64 %0, t; }"
        : "=r"(a) : "l"(p));
    return a;
}

__device__ __forceinline__ void ldsm_x4(uint32_t addr, uint32_t* r) {
    asm volatile("ldmatrix.sync.aligned.m8n8.x4.shared.b16 {%0,%1,%2,%3}, [%4];"
        : "=r"(r[0]), "=r"(r[1]), "=r"(r[2]), "=r"(r[3]) : "r"(addr));
}

__device__ __forceinline__ void ldsm_x4_t(uint32_t addr, uint32_t* r) {
    asm volatile("ldmatrix.sync.aligned.m8n8.x4.trans.shared.b16 {%0,%1,%2,%3}, [%4];"
        : "=r"(r[0]), "=r"(r[1]), "=r"(r[2]), "=r"(r[3]) : "r"(addr));
}

__device__ __forceinline__ void mma_bf16(float* d, const uint32_t* a,
                                         uint32_t b0, uint32_t b1) {
    asm volatile(
        "mma.sync.aligned.m16n8k16.row.col.f32.bf16.bf16.f32 "
        "{%0,%1,%2,%3}, {%4,%5,%6,%7}, {%8,%9}, {%0,%1,%2,%3};"
        : "+f"(d[0]), "+f"(d[1]), "+f"(d[2]), "+f"(d[3])
        : "r"(a[0]), "r"(a[1]), "r"(a[2]), "r"(a[3]), "r"(b0), "r"(b1));
}

__device__ __forceinline__ void split4(float4 v, uint2& hi, uint2& lo) {
    __nv_bfloat162 h0 = __floats2bfloat162_rn(v.x, v.y);
    __nv_bfloat162 h1 = __floats2bfloat162_rn(v.z, v.w);
    __nv_bfloat162 l0 = __floats2bfloat162_rn(v.x - __bfloat162float(h0.x),
                                              v.y - __bfloat162float(h0.y));
    __nv_bfloat162 l1 = __floats2bfloat162_rn(v.z - __bfloat162float(h1.x),
                                              v.w - __bfloat162float(h1.y));
    hi.x = *(uint32_t*)&h0; hi.y = *(uint32_t*)&h1;
    lo.x = *(uint32_t*)&l0; lo.y = *(uint32_t*)&l1;
}

__device__ __forceinline__ uint32_t pack_split(float x, float y, uint32_t& lo) {
    __nv_bfloat162 h = __floats2bfloat162_rn(x, y);
    __nv_bfloat162 l = __floats2bfloat162_rn(x - __bfloat162float(h.x),
                                             y - __bfloat162float(h.y));
    lo = *(uint32_t*)&l;
    return *(uint32_t*)&h;
}

__device__ __forceinline__ float ex2(float x) {
    float y;
    asm("ex2.approx.f32 %0, %1;" : "=f"(y) : "f"(x));
    return y;
}

__device__ __forceinline__ void cp16(uint32_t dst, const void* src) {
    asm volatile("cp.async.cg.shared.global [%0], [%1], 16;"
                 :: "r"(dst), "l"(src));
}
__device__ __forceinline__ void cp4(uint32_t dst, const void* src) {
    asm volatile("cp.async.ca.shared.global [%0], [%1], 4;"
                 :: "r"(dst), "l"(src));
}
#define CP_COMMIT() asm volatile("cp.async.commit_group;" ::: "memory")
#define CP_WAIT0()  asm volatile("cp.async.wait_group 0;" ::: "memory")

// ===========================================================================
// Split kernels
// ===========================================================================
__global__ void split_kernel(const float* __restrict__ src,
                             bf16* __restrict__ dh, bf16* __restrict__ dl,
                             int n4)
{
    int i = blockIdx.x * blockDim.x + threadIdx.x;
    if (i < n4) {
        float4 v = *(const float4*)(src + (size_t)i * 4);
        uint2 h, l;
        split4(v, h, l);
        *(uint2*)(dh + (size_t)i * 4) = h;
        *(uint2*)(dl + (size_t)i * 4) = l;
    }
}

// All 4 weights in one launch (sections of GK*GK each)
__global__ void split4w_kernel(const float* __restrict__ w0,
                               const float* __restrict__ w1,
                               const float* __restrict__ w2,
                               const float* __restrict__ w3,
                               bf16* __restrict__ dh, bf16* __restrict__ dl)
{
    const int per = GK * GK / 4;
    int i = blockIdx.x * blockDim.x + threadIdx.x;
    if (i >= 4 * per) return;
    int sec = i / per, off = i - sec * per;
    const float* src = (sec == 0) ? w0 : (sec == 1) ? w1 : (sec == 2) ? w2 : w3;
    float4 v = *(const float4*)(src + (size_t)off * 4);
    uint2 h, l;
    split4(v, h, l);
    *(uint2*)(dh + (size_t)sec * GK * GK + (size_t)off * 4) = h;
    *(uint2*)(dl + (size_t)sec * GK * GK + (size_t)off * 4) = l;
}

__global__ void concat_bias_kernel(const float* __restrict__ bq,
                                   const float* __restrict__ bk,
                                   const float* __restrict__ bv,
                                   float* __restrict__ dst)
{
    int i = blockIdx.x * blockDim.x + threadIdx.x;
    if (i < GK) dst[i] = bq[i];
    else if (i < 2 * GK) dst[i] = bk[i - GK];
    else if (i < 3 * GK) dst[i] = bv[i - 2 * GK];
}

// ===========================================================================
// GEMM: out = alpha*(A @ W^T + bias). Pre-split bf16 hi/lo operands.
// CTA 128x128, BK=32, 8 warps (64x32 each), cp.async double-buffered.
// Term-major MMA ordering: same-accumulator reuse distance = 16.
// ===========================================================================
#define GSTR 80
#define GTILE (128 * GSTR)
#define GSTAGE (4 * GTILE)
#define GEMM_SMEM_BYTES (2 * GSTAGE)

__global__ __launch_bounds__(256, 2)
void gemm_bf16_kernel(const bf16* __restrict__ Ah, const bf16* __restrict__ Al,
                      const bf16* __restrict__ Wh, const bf16* __restrict__ Wl,
                      const float* __restrict__ bias,
                      bf16* __restrict__ O0h, bf16* __restrict__ O0l,
                      bf16* __restrict__ O1h, bf16* __restrict__ O1l,
                      bf16* __restrict__ O2h, bf16* __restrict__ O2l,
                      float* __restrict__ Cf)
{
    extern __shared__ char smc[];
    const uint32_t sb = smem_u32(smc);
    const int tid  = threadIdx.x;
    const int lane = tid & 31;
    const int wid  = tid >> 5;
    const int bm = blockIdx.y * 128;
    const int bn = blockIdx.x * 128;
    const int wm = (wid & 1) * 64;
    const int wn = (wid >> 1) * 32;

    const int sec  = bn / GK;
    const int colb = bn - sec * GK;
    const float alpha = (Cf == nullptr && sec == 0) ? SCALEQ : 1.0f;
    bf16* Ho = (sec == 0) ? O0h : (sec == 1) ? O1h : O2h;
    bf16* Lo = (sec == 0) ? O0l : (sec == 1) ? O1l : O2l;

    const bf16* srcs[4] = { Ah + (size_t)bm * GK, Al + (size_t)bm * GK,
                            Wh + (size_t)bn * GK, Wl + (size_t)bn * GK };

    auto issue = [&](int s, int buf) {
        const uint32_t dbase = sb + (uint32_t)(buf * GSTAGE);
        #pragma unroll
        for (int p = 0; p < 4; p++) {
            const bf16* base = srcs[p] + s * 32;
            #pragma unroll
            for (int i = 0; i < 2; i++) {
                int idx = tid + i * 256;
                int row = idx >> 2, kc = idx & 3;
                cp16(dbase + (uint32_t)(p * GTILE + row * GSTR + kc * 16),
                     base + (size_t)row * GK + kc * 8);
            }
        }
    };

    issue(0, 0);
    CP_COMMIT();

    float acc[4][4][4] = {};
    const int frag_r = lane & 15;
    const int frag_k = (lane >> 4) << 3;

    #define KSTEPS24 24
    for (int s = 0; s < KSTEPS24; s++) {
        CP_WAIT0();
        __syncthreads();
        if (s + 1 < KSTEPS24) {
            issue(s + 1, (s + 1) & 1);
            CP_COMMIT();
        }
        const uint32_t stg = sb + (uint32_t)((s & 1) * GSTAGE);
        #pragma unroll
        for (int kk = 0; kk < 2; kk++) {
            const uint32_t kbyte = (uint32_t)((kk * 16 + frag_k) * 2);
            uint32_t ah[4][4], al[4][4], wh[2][4], wl[2][4];
            #pragma unroll
            for (int mi = 0; mi < 4; mi++) {
                uint32_t ro = (uint32_t)((wm + mi * 16 + frag_r) * GSTR) + kbyte;
                ldsm_x4(stg + 0 * GTILE + ro, ah[mi]);
                ldsm_x4(stg + 1 * GTILE + ro, al[mi]);
            }
            #pragma unroll
            for (int np = 0; np < 2; np++) {
                uint32_t ro = (uint32_t)((wn + np * 16 + frag_r) * GSTR) + kbyte;
                ldsm_x4(stg + 2 * GTILE + ro, wh[np]);
                ldsm_x4(stg + 3 * GTILE + ro, wl[np]);
            }
            // term-major: all hi*hi, then hi*lo, then lo*hi (16 independent accs)
            #pragma unroll
            for (int mi = 0; mi < 4; mi++)
                #pragma unroll
                for (int nj = 0; nj < 4; nj++) {
                    const int np = nj >> 1, sub = nj & 1;
                    mma_bf16(acc[mi][nj], ah[mi], wh[np][sub], wh[np][sub + 2]);
                }
            #pragma unroll
            for (int mi = 0; mi < 4; mi++)
                #pragma unroll
                for (int nj = 0; nj < 4; nj++) {
                    const int np = nj >> 1, sub = nj & 1;
                    mma_bf16(acc[mi][nj], ah[mi], wl[np][sub], wl[np][sub + 2]);
                }
            #pragma unroll
            for (int mi = 0; mi < 4; mi++)
                #pragma unroll
                for (int nj = 0; nj < 4; nj++) {
                    const int np = nj >> 1, sub = nj & 1;
                    mma_bf16(acc[mi][nj], al[mi], wh[np][sub], wh[np][sub + 2]);
                }
        }
        __syncthreads();
    }

    const int gr = lane >> 2;
    const int cp = (lane & 3) * 2;
    #pragma unroll
    for (int mi = 0; mi < 4; mi++) {
        #pragma unroll
        for (int nj = 0; nj < 4; nj++) {
            int row0 = bm + wm + mi * 16 + gr;
            int colg = colb + wn + nj * 8 + cp;
            int bcol = bn + wn + nj * 8 + cp;
            float b0 = bias[bcol], b1 = bias[bcol + 1];
            float v00 = alpha * (acc[mi][nj][0] + b0);
            float v01 = alpha * (acc[mi][nj][1] + b1);
            float v10 = alpha * (acc[mi][nj][2] + b0);
            float v11 = alpha * (acc[mi][nj][3] + b1);
            if (Cf) {
                float2 f0 = { v00, v01 }, f1 = { v10, v11 };
                *(float2*)&Cf[(size_t)row0 * GK + colg] = f0;
                *(float2*)&Cf[(size_t)(row0 + 8) * GK + colg] = f1;
            } else {
                uint32_t l0, l1;
                uint32_t h0 = pack_split(v00, v01, l0);
                uint32_t h1 = pack_split(v10, v11, l1);
                *(uint32_t*)&Ho[(size_t)row0 * GK + colg] = h0;
                *(uint32_t*)&Lo[(size_t)row0 * GK + colg] = l0;
                *(uint32_t*)&Ho[(size_t)(row0 + 8) * GK + colg] = h1;
                *(uint32_t*)&Lo[(size_t)(row0 + 8) * GK + colg] = l1;
            }
        }
    }
}

// ===========================================================================
// Flash attention, 4 warps x 32 q-rows (mi=2), k-tile 64.
// Term-major MMA ordering (same-acc distance 4). Bitwise-identical numerics.
// ===========================================================================
#define ASTR 144
#define AQH_O 0
#define AQL_O (128 * ASTR)
#define ASTG0 (2 * 128 * ASTR)
#define AKH_O 0
#define AKL_O (64 * ASTR)
#define AVH_O (2 * 64 * ASTR)
#define AVL_O (3 * 64 * ASTR)
#define AMSK_O (4 * 64 * ASTR)
#define ASTG_SZ (AMSK_O + 256)
#define ATTN_SMEM_BYTES (ASTG0 + 2 * ASTG_SZ)   // 111104

__global__ __launch_bounds__(128, 2)
void attn_bf16_kernel(const bf16* __restrict__ Qh, const bf16* __restrict__ Ql,
                      const bf16* __restrict__ Kh, const bf16* __restrict__ Kl,
                      const bf16* __restrict__ Vh, const bf16* __restrict__ Vl,
                      const float* __restrict__ mask,
                      bf16* __restrict__ Ch, bf16* __restrict__ Cl)
{
    extern __shared__ char smc[];
    const uint32_t sb = smem_u32(smc);
    const int b  = blockIdx.z;
    const int h  = blockIdx.y;
    const int qt = blockIdx.x;
    const int tid  = threadIdx.x;
    const int lane = tid & 31;
    const int wid  = tid >> 5;        // 0..3

    const int t  = lane & 3;
    const int gr = lane >> 2;
    const int frag_r = lane & 15;
    const int frag_k = (lane >> 4) << 3;
    const int v_kr = (lane & 7) + ((lane >> 4) << 3);
    const int v_nc = (lane & 8);

    const size_t qbase = ((size_t)b * S_LEN + (size_t)qt * 128) * GK + h * HD;

    auto issue_stage = [&](int kt, int buf) {
        const uint32_t dbase = sb + (uint32_t)(ASTG0 + buf * ASTG_SZ);
        const size_t off = ((size_t)b * S_LEN + (size_t)kt * 64) * GK + h * HD;
        const bf16* bases[4] = { Kh + off, Kl + off, Vh + off, Vl + off };
        #pragma unroll
        for (int p = 0; p < 4; p++) {
            #pragma unroll
            for (int i = 0; i < 4; i++) {
                int idx = tid + i * 128;
                int row = idx >> 3, kc = idx & 7;
                cp16(dbase + (uint32_t)(p * (64 * ASTR) + row * ASTR + kc * 16),
                     bases[p] + (size_t)row * GK + kc * 8);
            }
        }
        if (tid < 64)
            cp4(dbase + (uint32_t)(AMSK_O + tid * 4),
                mask + (size_t)b * S_LEN + kt * 64 + tid);
    };

    {
        #pragma unroll
        for (int i = 0; i < 8; i++) {
            int idx = tid + i * 128;
            int row = idx >> 3, kc = idx & 7;
            cp16(sb + (uint32_t)(AQH_O + row * ASTR + kc * 16),
                 Qh + qbase + (size_t)row * GK + kc * 8);
            cp16(sb + (uint32_t)(AQL_O + row * ASTR + kc * 16),
                 Ql + qbase + (size_t)row * GK + kc * 8);
        }
        issue_stage(0, 0);
        CP_COMMIT();
    }

    float o[2][8][4] = {};
    float m[2][2] = { { -1e30f, -1e30f }, { -1e30f, -1e30f } };
    float l[2][2] = {};

    for (int kt = 0; kt < S_LEN / 64; kt++) {
        CP_WAIT0();
        __syncthreads();
        if (kt + 1 < S_LEN / 64) {
            issue_stage(kt + 1, (kt + 1) & 1);
            CP_COMMIT();
        }
        const uint32_t stg = sb + (uint32_t)(ASTG0 + (kt & 1) * ASTG_SZ);
        const float* Ms = (const float*)(smc + ASTG0 + (kt & 1) * ASTG_SZ + AMSK_O);

        // ---- S = Q K^T (3-term split, term-major per np)
        float s[2][8][4] = {};
        #pragma unroll
        for (int kk = 0; kk < 4; kk++) {
            const uint32_t kbyte = (uint32_t)((kk * 16 + frag_k) * 2);
            uint32_t ah[2][4], al[2][4];
            #pragma unroll
            for (int mi = 0; mi < 2; mi++) {
                uint32_t qo = (uint32_t)((wid * 32 + mi * 16 + frag_r) * ASTR) + kbyte;
                ldsm_x4(sb + AQH_O + qo, ah[mi]);
                ldsm_x4(sb + AQL_O + qo, al[mi]);
            }
            #pragma unroll
            for (int np = 0; np < 4; np++) {
                uint32_t kh[4], kl[4];
                uint32_t ko = (uint32_t)((np * 16 + frag_r) * ASTR) + kbyte;
                ldsm_x4(stg + AKH_O + ko, kh);
                ldsm_x4(stg + AKL_O + ko, kl);
                #pragma unroll
                for (int sub = 0; sub < 2; sub++)
                    #pragma unroll
                    for (int mi = 0; mi < 2; mi++)
                        mma_bf16(s[mi][np * 2 + sub], ah[mi], kh[sub], kh[sub + 2]);
                #pragma unroll
                for (int sub = 0; sub < 2; sub++)
                    #pragma unroll
                    for (int mi = 0; mi < 2; mi++)
                        mma_bf16(s[mi][np * 2 + sub], ah[mi], kl[sub], kl[sub + 2]);
                #pragma unroll
                for (int sub = 0; sub < 2; sub++)
                    #pragma unroll
                    for (int mi = 0; mi < 2; mi++)
                        mma_bf16(s[mi][np * 2 + sub], al[mi], kh[sub], kh[sub + 2]);
            }
        }

        // ---- online softmax (exp2 domain)
        float bb0[8], bb1[8];
        #pragma unroll
        for (int nj = 0; nj < 8; nj++) {
            bb0[nj] = (1.0f - Ms[nj * 8 + 2 * t]) * (-10000.0f * LOG2E);
            bb1[nj] = (1.0f - Ms[nj * 8 + 2 * t + 1]) * (-10000.0f * LOG2E);
        }
        #pragma unroll
        for (int mi = 0; mi < 2; mi++) {
            float m0n = -1e30f, m1n = -1e30f;
            #pragma unroll
            for (int nj = 0; nj < 8; nj++) {
                s[mi][nj][0] += bb0[nj]; s[mi][nj][1] += bb1[nj];
                s[mi][nj][2] += bb0[nj]; s[mi][nj][3] += bb1[nj];
                m0n = fmaxf(m0n, fmaxf(s[mi][nj][0], s[mi][nj][1]));
                m1n = fmaxf(m1n, fmaxf(s[mi][nj][2], s[mi][nj][3]));
            }
            m0n = fmaxf(m0n, __shfl_xor_sync(0xffffffffu, m0n, 1));
            m0n = fmaxf(m0n, __shfl_xor_sync(0xffffffffu, m0n, 2));
            m1n = fmaxf(m1n, __shfl_xor_sync(0xffffffffu, m1n, 1));
            m1n = fmaxf(m1n, __shfl_xor_sync(0xffffffffu, m1n, 2));
            float m0w = fmaxf(m[mi][0], m0n);
            float m1w = fmaxf(m[mi][1], m1n);
            float a0 = ex2(m[mi][0] - m0w);
            float a1 = ex2(m[mi][1] - m1w);
            float sum0 = 0.0f, sum1 = 0.0f;
            #pragma unroll
            for (int nj = 0; nj < 8; nj++) {
                s[mi][nj][0] = ex2(s[mi][nj][0] - m0w);
                s[mi][nj][1] = ex2(s[mi][nj][1] - m0w);
                s[mi][nj][2] = ex2(s[mi][nj][2] - m1w);
                s[mi][nj][3] = ex2(s[mi][nj][3] - m1w);
                sum0 += s[mi][nj][0] + s[mi][nj][1];
                sum1 += s[mi][nj][2] + s[mi][nj][3];
            }
            l[mi][0] = l[mi][0] * a0 + sum0;
            l[mi][1] = l[mi][1] * a1 + sum1;
            m[mi][0] = m0w; m[mi][1] = m1w;
            #pragma unroll
            for (int nd = 0; nd < 8; nd++) {
                o[mi][nd][0] *= a0; o[mi][nd][1] *= a0;
                o[mi][nd][2] *= a1; o[mi][nd][3] *= a1;
            }
        }

        // ---- O += P V (3-term split, term-major per np; V via ldmatrix.trans)
        #pragma unroll
        for (int kk = 0; kk < 4; kk++) {
            const int j0 = 2 * kk, j1 = 2 * kk + 1;
            uint32_t pah[2][4], pal[2][4];
            #pragma unroll
            for (int mi = 0; mi < 2; mi++) {
                pah[mi][0] = pack_split(s[mi][j0][0], s[mi][j0][1], pal[mi][0]);
                pah[mi][1] = pack_split(s[mi][j0][2], s[mi][j0][3], pal[mi][1]);
                pah[mi][2] = pack_split(s[mi][j1][0], s[mi][j1][1], pal[mi][2]);
                pah[mi][3] = pack_split(s[mi][j1][2], s[mi][j1][3], pal[mi][3]);
            }
            #pragma unroll
            for (int np = 0; np < 4; np++) {
                uint32_t vh[4], vl[4];
                uint32_t vo = (uint32_t)((kk * 16 + v_kr) * ASTR
                                         + (np * 16 + v_nc) * 2);
                ldsm_x4_t(stg + AVH_O + vo, vh);
                ldsm_x4_t(stg + AVL_O + vo, vl);
                #pragma unroll
                for (int sub = 0; sub < 2; sub++)
                    #pragma unroll
                    for (int mi = 0; mi < 2; mi++)
                        mma_bf16(o[mi][np * 2 + sub], pah[mi], vh[sub], vh[sub + 2]);
                #pragma unroll
                for (int sub = 0; sub < 2; sub++)
                    #pragma unroll
                    for (int mi = 0; mi < 2; mi++)
                        mma_bf16(o[mi][np * 2 + sub], pah[mi], vl[sub], vl[sub + 2]);
                #pragma unroll
                for (int sub = 0; sub < 2; sub++)
                    #pragma unroll
                    for (int mi = 0; mi < 2; mi++)
                        mma_bf16(o[mi][np * 2 + sub], pal[mi], vh[sub], vh[sub + 2]);
            }
        }
        __syncthreads();
    }

    // final l reduce + write out (pre-split bf16)
    #pragma unroll
    for (int mi = 0; mi < 2; mi++) {
        float l0 = l[mi][0], l1 = l[mi][1];
        l0 += __shfl_xor_sync(0xffffffffu, l0, 1);
        l0 += __shfl_xor_sync(0xffffffffu, l0, 2);
        l1 += __shfl_xor_sync(0xffffffffu, l1, 1);
        l1 += __shfl_xor_sync(0xffffffffu, l1, 2);
        float inv0 = 1.0f / l0;
        float inv1 = 1.0f / l1;

        const size_t row0 = (size_t)b * S_LEN + (size_t)qt * 128
                          + wid * 32 + mi * 16 + gr;
        const size_t cb = row0 * GK + h * HD;
        #pragma unroll
        for (int nd = 0; nd < 8; nd++) {
            int col = nd * 8 + 2 * t;
            uint32_t lo0, lo1;
            uint32_t h0 = pack_split(o[mi][nd][0] * inv0, o[mi][nd][1] * inv0, lo0);
            uint32_t h1 = pack_split(o[mi][nd][2] * inv1, o[mi][nd][3] * inv1, lo1);
            *(uint32_t*)&Ch[cb + col] = h0;
            *(uint32_t*)&Cl[cb + col] = lo0;
            *(uint32_t*)&Ch[cb + (size_t)8 * GK + col] = h1;
            *(uint32_t*)&Cl[cb + (size_t)8 * GK + col] = lo1;
        }
    }
}

// ---------------------------------------------------------------------------
extern "C" void kernel_launch(void* const* d_in, const int* in_sizes, int n_in,
                              void* d_out, int out_size)
{
    const float* X    = (const float*)d_in[0];
    const float* mask = (const float*)d_in[1];
    const float* Wq   = (const float*)d_in[2];
    const float* bq   = (const float*)d_in[3];
    const float* Wk   = (const float*)d_in[4];
    const float* bk   = (const float*)d_in[5];
    const float* Wv   = (const float*)d_in[6];
    const float* bv   = (const float*)d_in[7];
    const float* Wo   = (const float*)d_in[8];
    const float* bo   = (const float*)d_in[9];
    float* out = (float*)d_out;

    bf16 *xh, *xl, *wh, *wl, *qh, *ql, *kh, *kl, *vh, *vl, *ch, *cl;
    float* b3;
    cudaGetSymbolAddress((void**)&xh, g_Xh);
    cudaGetSymbolAddress((void**)&xl, g_Xl);
    cudaGetSymbolAddress((void**)&wh, g_Wh);
    cudaGetSymbolAddress((void**)&wl, g_Wl);
    cudaGetSymbolAddress((void**)&qh, g_Qh);
    cudaGetSymbolAddress((void**)&ql, g_Ql);
    cudaGetSymbolAddress((void**)&kh, g_Kh);
    cudaGetSymbolAddress((void**)&kl, g_Kl);
    cudaGetSymbolAddress((void**)&vh, g_Vh);
    cudaGetSymbolAddress((void**)&vl, g_Vl);
    cudaGetSymbolAddress((void**)&ch, g_Ch);
    cudaGetSymbolAddress((void**)&cl, g_Cl);
    cudaGetSymbolAddress((void**)&b3, g_bias3);

    cudaFuncSetAttribute(gemm_bf16_kernel,
                         cudaFuncAttributeMaxDynamicSharedMemorySize,
                         GEMM_SMEM_BYTES);
    cudaFuncSetAttribute(attn_bf16_kernel,
                         cudaFuncAttributeMaxDynamicSharedMemorySize,
                         ATTN_SMEM_BYTES);

    // pre-split inputs (X + all 4 weights in one launch) + bias concat
    split_kernel<<<(M_TOTAL * GK / 4 + 255) / 256, 256>>>(X, xh, xl, M_TOTAL * GK / 4);
    split4w_kernel<<<(4 * GK * GK / 4 + 255) / 256, 256>>>(Wq, Wk, Wv, Wo, wh, wl);
    concat_bias_kernel<<<(3 * GK + 255) / 256, 256>>>(bq, bk, bv, b3);

    // fused QKV projection: N = 2304
    dim3 fgrid(3 * GK / 128, M_TOTAL / 128);   // (18, 64)
    gemm_bf16_kernel<<<fgrid, 256, GEMM_SMEM_BYTES>>>(
        xh, xl, wh, wl, b3, qh, ql, kh, kl, vh, vl, nullptr);

    dim3 agrid(S_LEN / 128, NH, B_SZ);         // (16, 12, 4)
    attn_bf16_kernel<<<agrid, 128, ATTN_SMEM_BYTES>>>(
        qh, ql, kh, kl, vh, vl, mask, ch, cl);

    // output projection (fp32 out)
    dim3 ogrid(GK / 128, M_TOTAL / 128);       // (6, 64)
    gemm_bf16_kernel<<<ogrid, 256, GEMM_SMEM_BYTES>>>(
        ch, cl, wh + 3 * GK * GK, wl + 3 * GK * GK, bo,
        nullptr, nullptr, nullptr, nullptr, nullptr, nullptr, out);
}